// round 7
// baseline (speedup 1.0000x reference)
#include <cuda_runtime.h>
#include <cuda_fp16.h>
#include <math.h>
#include <cstdint>

#define Bsz 32
#define Nn  100
#define Ee  9900
#define Hh  256
#define FIN 200
#define BE  (Bsz*Ee)    // 316800
#define BNr (Bsz*Nn)    // 3200
#define NCTA (BE/128)   // 2475

// ---------------- scratch (static device globals) ---------------------------
__device__ float g_h1[BNr*Hh];
__device__ float g_na[BNr*Hh];
__device__ float g_nb[BNr*Hh];
__device__ float g_as[BNr*Hh];
__device__ float g_ar[BNr*Hh];
__device__ float g_xskip[(size_t)BE*Hh];
__device__ float g_pre[(size_t)BE*Hh];
__device__ float g_y4[(size_t)BE*Hh];
__device__ int   g_send[Ee];
__device__ int   g_recv[Ee];
__device__ float g_p3[(size_t)NCTA*256*2];   // per-CTA BN partials (sum, sumsq)
__device__ double g_chS[256], g_chQ[256];
__device__ float g_fcW[Hh*2];
__device__ float g_fcB[2];
// transposed fp16-split weight images: [n][k] layout, 3 mats
__device__ __half g_WtHi[3][65536];
__device__ __half g_WtLo[3][65536];

__device__ __forceinline__ float elu_f(float x) { return x > 0.f ? x : expm1f(x); }
// fast ELU: MUFU-based; abs error ~2e-7, negligible vs fp16 rounding downstream
__device__ __forceinline__ float elu_fast(float x) {
    float e = __expf(fminf(x, 0.f)) - 1.f;
    return x > 0.f ? x : e;
}

__device__ __forceinline__ uint32_t smem_u32(const void* p) {
    uint32_t a;
    asm("{ .reg .u64 t; cvta.to.shared.u64 t, %1; cvt.u32.u64 %0, t; }" : "=r"(a) : "l"(p));
    return a;
}
__device__ __forceinline__ uint32_t pack_h2(__half a, __half b) {
    __half2 h2 = __halves2half2(a, b);
    return *reinterpret_cast<uint32_t*>(&h2);
}

#define LDSM4(r, addr) \
    asm volatile("ldmatrix.sync.aligned.m8n8.x4.shared.b16 {%0,%1,%2,%3}, [%4];" \
        : "=r"((r)[0]), "=r"((r)[1]), "=r"((r)[2]), "=r"((r)[3]) : "r"(addr))

#define MMA16816(d, a, b0, b1) \
    asm volatile("mma.sync.aligned.m16n8k16.row.col.f32.f16.f16.f32 " \
        "{%0,%1,%2,%3},{%4,%5,%6,%7},{%8,%9},{%0,%1,%2,%3};" \
        : "+f"((d)[0]), "+f"((d)[1]), "+f"((d)[2]), "+f"((d)[3]) \
        : "r"((a)[0]), "r"((a)[1]), "r"((a)[2]), "r"((a)[3]), "r"(b0), "r"(b1))

#define CP16(dst, src) \
    asm volatile("cp.async.ca.shared.global [%0], [%1], 16;" :: "r"(dst), "l"(src))
#define CP_COMMIT() asm volatile("cp.async.commit_group;" ::: "memory")
#define CP_WAIT0()  asm volatile("cp.async.wait_group 0;" ::: "memory")

// ---------------- edge index extraction -------------------------------------
__global__ void build_idx_k(const float* __restrict__ rr, const float* __restrict__ rs) {
    int e = blockIdx.x * blockDim.x + threadIdx.x;
    if (e >= Ee) return;
    int r = 0, s = 0;
    for (int n = 0; n < Nn; n++) {
        if (rr[e*Nn + n] > 0.5f) r = n;
        if (rs[e*Nn + n] > 0.5f) s = n;
    }
    g_recv[e] = r;
    g_send[e] = s;
}

// ---------------- weight prep: transpose [k][n]->[n][k] + fp16 split --------
__global__ void prep_wt_k(const float* __restrict__ W,
                          __half* __restrict__ Hi, __half* __restrict__ Lo) {
    __shared__ float t[32][33];
    int k0 = blockIdx.x * 32, n0 = blockIdx.y * 32;
    int tx = threadIdx.x, ty = threadIdx.y;
    t[ty][tx] = W[(k0 + ty) * 256 + n0 + tx];
    __syncthreads();
    float v = t[tx][ty];            // element (k = k0+tx, n = n0+ty)
    __half h = __float2half_rn(v);
    __half l = __float2half_rn(v - __half2float(h));
    Hi[(n0 + ty) * 256 + k0 + tx] = h;
    Lo[(n0 + ty) * 256 + k0 + tx] = l;
}

// ---------------- big tensor-core GEMM: one-shot stage, pure-MMA mainloop ---
// CTA: 128 rows x 128 cols, K=256. 1 CTA/SM, 198KB smem.
// Prologue: cp.async full B (hi+lo, 128KB) + build full A fp16 tile (66KB).
// Mainloop: 8 chunks x (LDSM + MMA) with NO barriers / LDG / conversion.
// AMODE 0: A = Amat
// AMODE 1: A = ELU(As[s]+Ar[r]+b1)
// AMODE 2: A = ELU(Amat + As[s]+Ar[r]+b1), plus BN partials in epilogue
#define ASTR  528
#define AOF   0
#define BHIOF 67584
#define BLOOF 135168
#define DSMT  202752

template<int AMODE>
__global__ __launch_bounds__(256, 1)
void gemm_tc(const float* __restrict__ Amat,
             const __half* __restrict__ WtHi, const __half* __restrict__ WtLo,
             const float* __restrict__ As_, const float* __restrict__ Ar_,
             const float* __restrict__ b1,
             const float* __restrict__ bias, int do_elu,
             float* __restrict__ C)
{
    extern __shared__ char sm[];
    __shared__ int sidx[128], ridx[128];

    const int tid  = threadIdx.x;
    const int lane = tid & 31, w = tid >> 5;
    const int row0 = blockIdx.x * 128;
    const int nbase = blockIdx.y * 128;
    const uint32_t sbase = smem_u32(sm);

    // ---- issue full-B cp.async immediately (overlaps everything below)
    #pragma unroll 8
    for (int i = 0; i < 32; ++i) {
        int seg = tid + i * 256;          // 0..8191
        int isLo = seg >> 12;             // 0: hi, 1: lo
        int row  = (seg >> 5) & 127;
        int q    = seg & 31;
        const __half* src = (isLo ? WtLo : WtHi) + (size_t)(nbase + row) * 256 + q * 8;
        uint32_t dst = sbase + (isLo ? BLOOF : BHIOF) + row * ASTR + q * 16;
        CP16(dst, (const char*)src);
    }
    CP_COMMIT();

    if (AMODE != 0 && tid < 128) {
        int row = row0 + tid;
        int b = row / Ee, e = row - b * Ee;
        sidx[tid] = (b * Nn + g_send[e]) * Hh;
        ridx[tid] = (b * Nn + g_recv[e]) * Hh;
    }
    __syncthreads();   // sidx/ridx visible

    // ---- build full A fp16 tile: thread = (row, col-half of 128)
    {
        const int row  = tid >> 1;
        const int colb = (tid & 1) * 128;
        const size_t arow = (size_t)(row0 + row) * 256;
        int si = 0, ri = 0;
        if (AMODE != 0) { si = sidx[row]; ri = ridx[row]; }
        char* adst = sm + AOF + row * ASTR + colb * 2;
        #pragma unroll 4
        for (int it = 0; it < 16; ++it) {
            int k0 = colb + it * 8;
            float4 t0, t1;
            if (AMODE == 0) {
                t0 = *(const float4*)(Amat + arow + k0);
                t1 = *(const float4*)(Amat + arow + k0 + 4);
            } else {
                float4 s0 = *(const float4*)(As_ + si + k0);
                float4 s1 = *(const float4*)(As_ + si + k0 + 4);
                float4 r0 = *(const float4*)(Ar_ + ri + k0);
                float4 r1 = *(const float4*)(Ar_ + ri + k0 + 4);
                float4 c0 = *(const float4*)(b1 + k0);
                float4 c1 = *(const float4*)(b1 + k0 + 4);
                t0.x = s0.x + r0.x + c0.x; t0.y = s0.y + r0.y + c0.y;
                t0.z = s0.z + r0.z + c0.z; t0.w = s0.w + r0.w + c0.w;
                t1.x = s1.x + r1.x + c1.x; t1.y = s1.y + r1.y + c1.y;
                t1.z = s1.z + r1.z + c1.z; t1.w = s1.w + r1.w + c1.w;
                if (AMODE == 2) {
                    float4 p0 = *(const float4*)(Amat + arow + k0);
                    float4 p1 = *(const float4*)(Amat + arow + k0 + 4);
                    t0.x += p0.x; t0.y += p0.y; t0.z += p0.z; t0.w += p0.w;
                    t1.x += p1.x; t1.y += p1.y; t1.z += p1.z; t1.w += p1.w;
                }
                t0.x = elu_fast(t0.x); t0.y = elu_fast(t0.y);
                t0.z = elu_fast(t0.z); t0.w = elu_fast(t0.w);
                t1.x = elu_fast(t1.x); t1.y = elu_fast(t1.y);
                t1.z = elu_fast(t1.z); t1.w = elu_fast(t1.w);
            }
            uint4 o;
            o.x = pack_h2(__float2half_rn(t0.x), __float2half_rn(t0.y));
            o.y = pack_h2(__float2half_rn(t0.z), __float2half_rn(t0.w));
            o.z = pack_h2(__float2half_rn(t1.x), __float2half_rn(t1.y));
            o.w = pack_h2(__float2half_rn(t1.z), __float2half_rn(t1.w));
            *(uint4*)(adst + it * 16) = o;
        }
    }
    CP_WAIT0();
    __syncthreads();   // A + B tiles complete

    // ---- per-warp tile origin + ldmatrix lane addresses
    const int m0w = (w & 3) * 32;
    const int n0w = (w >> 2) * 64;
    const int laneA_row = (lane & 7) + ((lane >> 3) & 1) * 8;
    const int laneA_k   = ((lane >> 4) & 1) * 8;
    const int laneB_row = (lane & 7) + ((lane >> 4) & 1) * 8;
    const int laneB_k   = ((lane >> 3) & 1) * 8;

    uint32_t aAd[2], bAd[4];
    #pragma unroll
    for (int i = 0; i < 2; i++)
        aAd[i] = sbase + AOF + (uint32_t)((m0w + i*16 + laneA_row) * ASTR + laneA_k * 2);
    #pragma unroll
    for (int jp = 0; jp < 4; jp++)
        bAd[jp] = sbase + BHIOF + (uint32_t)((n0w + jp*16 + laneB_row) * ASTR + laneB_k * 2);

    float acc[16][4];
    #pragma unroll
    for (int t = 0; t < 16; t++) { acc[t][0]=0.f; acc[t][1]=0.f; acc[t][2]=0.f; acc[t][3]=0.f; }

    // ---- pure MMA mainloop: no barriers, no LDG, no conversion
    #pragma unroll 1
    for (int c = 0; c < 8; ++c) {
        const uint32_t ko = (uint32_t)(c * 64);   // (c*32 k) * 2 bytes
        #pragma unroll
        for (int ks = 0; ks < 2; ++ks) {
            uint32_t ah[2][4];
            #pragma unroll
            for (int i = 0; i < 2; i++)
                LDSM4(ah[i], aAd[i] + ko + ks * 32);
            #pragma unroll
            for (int jp = 0; jp < 4; jp++) {
                uint32_t bh4[4], bl4[4];
                LDSM4(bh4, bAd[jp] + ko + ks * 32);
                LDSM4(bl4, bAd[jp] + (BLOOF - BHIOF) + ko + ks * 32);
                MMA16816(acc[0*8+2*jp],   ah[0], bh4[0], bh4[1]);
                MMA16816(acc[0*8+2*jp+1], ah[0], bh4[2], bh4[3]);
                MMA16816(acc[1*8+2*jp],   ah[1], bh4[0], bh4[1]);
                MMA16816(acc[1*8+2*jp+1], ah[1], bh4[2], bh4[3]);
                MMA16816(acc[0*8+2*jp],   ah[0], bl4[0], bl4[1]);
                MMA16816(acc[0*8+2*jp+1], ah[0], bl4[2], bl4[3]);
                MMA16816(acc[1*8+2*jp],   ah[1], bl4[0], bl4[1]);
                MMA16816(acc[1*8+2*jp+1], ah[1], bl4[2], bl4[3]);
            }
        }
    }

    // ---- epilogue: bias + ELU, fp32 stores (+ BN partials for AMODE 2)
    const int g  = lane >> 2;
    const int tg = lane & 3;
    float cs[16], cq[16];
    if (AMODE == 2) {
        #pragma unroll
        for (int t = 0; t < 16; ++t) { cs[t] = 0.f; cq[t] = 0.f; }
    }
    #pragma unroll
    for (int i = 0; i < 2; i++) {
        #pragma unroll
        for (int j = 0; j < 8; j++) {
            int colg = nbase + n0w + j*8 + tg*2;
            float b0v = 0.f, b1v = 0.f;
            if (bias) { b0v = __ldg(bias + colg); b1v = __ldg(bias + colg + 1); }
            float* q = acc[i*8+j];
            int rlo = row0 + m0w + i*16 + g;
            int rhi = rlo + 8;
            float2 o0, o1;
            o0.x = q[0] + b0v; o0.y = q[1] + b1v;
            o1.x = q[2] + b0v; o1.y = q[3] + b1v;
            if (do_elu) {
                o0.x = elu_f(o0.x); o0.y = elu_f(o0.y);
                o1.x = elu_f(o1.x); o1.y = elu_f(o1.y);
            }
            if (AMODE == 2) {
                cs[j*2+0] += o0.x + o1.x;
                cs[j*2+1] += o0.y + o1.y;
                cq[j*2+0] += o0.x*o0.x + o1.x*o1.x;
                cq[j*2+1] += o0.y*o0.y + o1.y*o1.y;
            }
            *(float2*)(C + (size_t)rlo * 256 + colg) = o0;
            *(float2*)(C + (size_t)rhi * 256 + colg) = o1;
        }
    }

    if (AMODE == 2) {
        #pragma unroll
        for (int t = 0; t < 16; ++t) {
            #pragma unroll
            for (int o = 4; o <= 16; o <<= 1) {
                cs[t] += __shfl_xor_sync(0xffffffffu, cs[t], o);
                cq[t] += __shfl_xor_sync(0xffffffffu, cq[t], o);
            }
        }
        __syncthreads();
        float* sps = (float*)sm;         // [8 warps][64 cols][2]
        if (lane < 4) {
            #pragma unroll
            for (int j = 0; j < 8; ++j) {
                #pragma unroll
                for (int par = 0; par < 2; ++par) {
                    int col = j*8 + lane*2 + par;
                    sps[(w*64 + col)*2 + 0] = cs[j*2+par];
                    sps[(w*64 + col)*2 + 1] = cq[j*2+par];
                }
            }
        }
        __syncthreads();
        int strip = tid >> 7, col = (tid >> 1) & 63, stat = tid & 1;
        float a2 = 0.f;
        #pragma unroll
        for (int wi = 0; wi < 4; ++wi)
            a2 += sps[((strip*4 + wi)*64 + col)*2 + stat];
        int ch = nbase + strip*64 + col;
        g_p3[((size_t)blockIdx.x * 256 + ch)*2 + stat] = a2;
    }
}

// ---------------- small node-level SIMT GEMM (M=3200) -----------------------
__global__ __launch_bounds__(256)
void gemm_node(const float* __restrict__ A, int lda, int K,
               const float* __restrict__ W, const float* __restrict__ bias,
               int do_elu, float* __restrict__ C)
{
    __shared__ float sA[16][65];
    __shared__ float sB[16][64];
    const int row0 = blockIdx.x * 64;
    const int col0 = blockIdx.y * 64;
    const int tid  = threadIdx.x;
    const int ty   = tid >> 4, tx = tid & 15;
    float acc[4][4] = {};
    for (int kt = 0; kt < K; kt += 16) {
        #pragma unroll
        for (int i = 0; i < 4; i++) {
            int idx = tid + i * 256;
            int m = idx >> 4, k = idx & 15;
            int kk = kt + k;
            sA[k][m] = (kk < K) ? A[(size_t)(row0 + m) * lda + kk] : 0.f;
        }
        #pragma unroll
        for (int i = 0; i < 4; i++) {
            int idx = tid + i * 256;
            int k = idx >> 6, n = idx & 63;
            int kk = kt + k;
            sB[k][n] = (kk < K) ? W[(size_t)kk * 256 + col0 + n] : 0.f;
        }
        __syncthreads();
        #pragma unroll
        for (int k = 0; k < 16; k++) {
            float a[4], b[4];
            #pragma unroll
            for (int i = 0; i < 4; i++) a[i] = sA[k][ty*4 + i];
            #pragma unroll
            for (int j = 0; j < 4; j++) b[j] = sB[k][tx*4 + j];
            #pragma unroll
            for (int i = 0; i < 4; i++)
                #pragma unroll
                for (int j = 0; j < 4; j++)
                    acc[i][j] += a[i] * b[j];
        }
        __syncthreads();
    }
    #pragma unroll
    for (int i = 0; i < 4; i++) {
        int m = row0 + ty*4 + i;
        #pragma unroll
        for (int j = 0; j < 4; j++) {
            int n = col0 + tx*4 + j;
            float v = acc[i][j];
            if (bias) v += bias[n];
            if (do_elu) v = elu_f(v);
            C[(size_t)m * 256 + n] = v;
        }
    }
}

// ---------------- merged dual node GEMM: same A, two weight mats ------------
__global__ __launch_bounds__(256)
void gemm_node2(const float* __restrict__ A,
                const float* __restrict__ Wa, const float* __restrict__ Wb,
                float* __restrict__ Ca, float* __restrict__ Cb)
{
    const float* W = (blockIdx.y < 4) ? Wa : Wb;
    float* C       = (blockIdx.y < 4) ? Ca : Cb;
    const int col0 = (blockIdx.y & 3) * 64;
    __shared__ float sA[16][65];
    __shared__ float sB[16][64];
    const int row0 = blockIdx.x * 64;
    const int tid  = threadIdx.x;
    const int ty   = tid >> 4, tx = tid & 15;
    float acc[4][4] = {};
    for (int kt = 0; kt < 256; kt += 16) {
        #pragma unroll
        for (int i = 0; i < 4; i++) {
            int idx = tid + i * 256;
            int m = idx >> 4, k = idx & 15;
            sA[k][m] = A[(size_t)(row0 + m) * 256 + kt + k];
        }
        #pragma unroll
        for (int i = 0; i < 4; i++) {
            int idx = tid + i * 256;
            int k = idx >> 6, n = idx & 63;
            sB[k][n] = W[(size_t)(kt + k) * 256 + col0 + n];
        }
        __syncthreads();
        #pragma unroll
        for (int k = 0; k < 16; k++) {
            float a[4], b[4];
            #pragma unroll
            for (int i = 0; i < 4; i++) a[i] = sA[k][ty*4 + i];
            #pragma unroll
            for (int j = 0; j < 4; j++) b[j] = sB[k][tx*4 + j];
            #pragma unroll
            for (int i = 0; i < 4; i++)
                #pragma unroll
                for (int j = 0; j < 4; j++)
                    acc[i][j] += a[i] * b[j];
        }
        __syncthreads();
    }
    #pragma unroll
    for (int i = 0; i < 4; i++) {
        int m = row0 + ty*4 + i;
        #pragma unroll
        for (int j = 0; j < 4; j++)
            C[(size_t)m * 256 + col0 + tx*4 + j] = acc[i][j];
    }
}

// ---------------- edge2node: contiguous 99-edge segment mean ----------------
__global__ void edge2node_k(const float* __restrict__ x, float* __restrict__ out) {
    int nodeRow = blockIdx.x;
    int h = threadIdx.x;
    int b = nodeRow / Nn, n = nodeRow - b * Nn;
    const float* base = x + (size_t)(b * Ee + n * 99) * Hh + h;
    float s = 0.f;
    #pragma unroll 3
    for (int r = 0; r < 99; r++) s += base[(size_t)r * Hh];
    out[(size_t)nodeRow * Hh + h] = s * (1.0f / 9900.0f);
}

// ---------------- BN partial reduce: parallel deterministic tree ------------
__global__ void bn_reduce_k() {
    int ch = blockIdx.x, t = threadIdx.x;
    double s = 0.0, q = 0.0;
    for (int bx = t; bx < NCTA; bx += 256) {
        s += (double)g_p3[((size_t)bx * 256 + ch) * 2 + 0];
        q += (double)g_p3[((size_t)bx * 256 + ch) * 2 + 1];
    }
    __shared__ double ss[256], sq[256];
    ss[t] = s; sq[t] = q;
    __syncthreads();
    for (int st = 128; st > 0; st >>= 1) {
        if (t < st) { ss[t] += ss[t + st]; sq[t] += sq[t + st]; }
        __syncthreads();
    }
    if (t == 0) { g_chS[ch] = ss[0]; g_chQ[ch] = sq[0]; }
}

// ---------------- BN finalize + fold into fc --------------------------------
__global__ void bn_fin3(const float* __restrict__ gamma, const float* __restrict__ beta,
                        const float* __restrict__ W, const float* __restrict__ fb) {
    int ch = threadIdx.x;
    double s = g_chS[ch], q = g_chQ[ch];
    double m = s / (double)BE;
    double v = q / (double)BE - m * m;
    float sc = (float)(rsqrt(v + 1e-5) * (double)gamma[ch]);
    float sh = beta[ch] - (float)m * sc;
    float w0 = W[ch*2 + 0], w1 = W[ch*2 + 1];
    g_fcW[ch*2 + 0] = sc * w0;
    g_fcW[ch*2 + 1] = sc * w1;
    __shared__ float r0s[256], r1s[256];
    r0s[ch] = sh * w0;
    r1s[ch] = sh * w1;
    __syncthreads();
    for (int st = 128; st > 0; st >>= 1) {
        if (ch < st) { r0s[ch] += r0s[ch + st]; r1s[ch] += r1s[ch + st]; }
        __syncthreads();
    }
    if (ch == 0) { g_fcB[0] = r0s[0] + fb[0]; g_fcB[1] = r1s[0] + fb[1]; }
}

// ---------------- final fc (folded BN): warp per row ------------------------
__global__ void fc_k(const float* __restrict__ y, float* __restrict__ out) {
    int gwarp = (blockIdx.x * blockDim.x + threadIdx.x) >> 5;
    int lane  = threadIdx.x & 31;
    if (gwarp >= BE) return;
    const float* row = y + (size_t)gwarp * Hh;
    float a0 = 0.f, a1 = 0.f;
    #pragma unroll
    for (int i = lane; i < Hh; i += 32) {
        float v = row[i];
        a0 += v * g_fcW[i*2 + 0];
        a1 += v * g_fcW[i*2 + 1];
    }
    #pragma unroll
    for (int o = 16; o > 0; o >>= 1) {
        a0 += __shfl_down_sync(0xffffffffu, a0, o);
        a1 += __shfl_down_sync(0xffffffffu, a1, o);
    }
    if (lane == 0) {
        out[(size_t)gwarp * 2 + 0] = a0 + g_fcB[0];
        out[(size_t)gwarp * 2 + 1] = a1 + g_fcB[1];
    }
}

// ---------------------------------------------------------------------------
extern "C" void kernel_launch(void* const* d_in, const int* in_sizes, int n_in,
                              void* d_out, int out_size) {
    const float* inputs  = (const float*)d_in[0];
    const float* rel_rec = (const float*)d_in[1];
    const float* rel_snd = (const float*)d_in[2];
    const float* m1W1 = (const float*)d_in[3];  const float* m1b1 = (const float*)d_in[4];
    const float* m1W2 = (const float*)d_in[5];  const float* m1b2 = (const float*)d_in[6];
    const float* m2W1 = (const float*)d_in[7];  const float* m2b1 = (const float*)d_in[8];
    const float* m2W2 = (const float*)d_in[9];  const float* m2b2 = (const float*)d_in[10];
    const float* m3W1 = (const float*)d_in[11]; const float* m3b1 = (const float*)d_in[12];
    const float* m3W2 = (const float*)d_in[13]; const float* m3b2 = (const float*)d_in[14];
    const float* m4W1 = (const float*)d_in[15]; const float* m4b1 = (const float*)d_in[16];
    const float* m4W2 = (const float*)d_in[17]; const float* m4b2 = (const float*)d_in[18];
    const float* gmma = (const float*)d_in[19]; const float* beta = (const float*)d_in[20];
    const float* fcW  = (const float*)d_in[21]; const float* fcb  = (const float*)d_in[22];
    float* out = (float*)d_out;

    float *h1, *na, *nb, *as_, *ar_, *xskip, *pre, *y4;
    __half *wth, *wtl;
    cudaGetSymbolAddress((void**)&h1, g_h1);
    cudaGetSymbolAddress((void**)&na, g_na);
    cudaGetSymbolAddress((void**)&nb, g_nb);
    cudaGetSymbolAddress((void**)&as_, g_as);
    cudaGetSymbolAddress((void**)&ar_, g_ar);
    cudaGetSymbolAddress((void**)&xskip, g_xskip);
    cudaGetSymbolAddress((void**)&pre, g_pre);
    cudaGetSymbolAddress((void**)&y4, g_y4);
    cudaGetSymbolAddress((void**)&wth, g_WtHi);
    cudaGetSymbolAddress((void**)&wtl, g_WtLo);

    cudaFuncSetAttribute(gemm_tc<0>, cudaFuncAttributeMaxDynamicSharedMemorySize, DSMT);
    cudaFuncSetAttribute(gemm_tc<1>, cudaFuncAttributeMaxDynamicSharedMemorySize, DSMT);
    cudaFuncSetAttribute(gemm_tc<2>, cudaFuncAttributeMaxDynamicSharedMemorySize, DSMT);

    dim3 gN(BNr / 64, 4);
    dim3 gN2(BNr / 64, 8);
    dim3 gE(NCTA, 2);
    dim3 tb(32, 32);
    dim3 tg(8, 8);

    // edge index tables + weight prep (transpose + fp16 split)
    build_idx_k<<<(Ee + 127) / 128, 128>>>(rel_rec, rel_snd);
    prep_wt_k<<<tg, tb>>>(m2W2,             wth + 0 * 65536, wtl + 0 * 65536);
    prep_wt_k<<<tg, tb>>>(m4W1 + 512 * 256, wth + 1 * 65536, wtl + 1 * 65536);
    prep_wt_k<<<tg, tb>>>(m4W2,             wth + 2 * 65536, wtl + 2 * 65536);

    // mlp1 (node level)
    gemm_node<<<gN, 256>>>(inputs, FIN, FIN, m1W1, m1b1, 1, na);
    gemm_node<<<gN, 256>>>(na, Hh, Hh, m1W2, m1b2, 1, h1);

    // node projections for mlp2 layer1 (send + recv halves, one launch)
    gemm_node2<<<gN2, 256>>>(h1, m2W1, m2W1 + 256*256, as_, ar_);

    // big GEMM #1 (tensor): xskip = ELU(ELU(as[s]+ar[r]+b1) @ W2 + b2)
    gemm_tc<1><<<gE, 256, DSMT>>>(nullptr, wth + 0 * 65536, wtl + 0 * 65536,
                                  as_, ar_, m2b1, m2b2, 1, xskip);

    // edge2node + mlp3 (node level)
    edge2node_k<<<BNr, 256>>>(xskip, na);
    gemm_node<<<gN, 256>>>(na, Hh, Hh, m3W1, m3b1, 1, nb);
    gemm_node<<<gN, 256>>>(nb, Hh, Hh, m3W2, m3b2, 1, h1);

    // node projections for mlp4 layer1
    gemm_node2<<<gN2, 256>>>(h1, m4W1, m4W1 + 256*256, as_, ar_);

    // big GEMM #2 (tensor): pre = xskip @ W4_1[512:768]
    gemm_tc<0><<<gE, 256, DSMT>>>(xskip, wth + 1 * 65536, wtl + 1 * 65536,
                                  nullptr, nullptr, nullptr, nullptr, 0, pre);

    // big GEMM #3 (tensor): y4 = ELU(ELU(pre + as[s]+ar[r]+b1) @ W4_2 + b2)
    //                        + fused per-CTA BN partial stats
    gemm_tc<2><<<gE, 256, DSMT>>>(pre, wth + 2 * 65536, wtl + 2 * 65536,
                                  as_, ar_, m4b1, m4b2, 1, y4);

    // BN reduce (parallel deterministic), finalize, final fc
    bn_reduce_k<<<256, 256>>>();
    bn_fin3<<<1, 256>>>(gmma, beta, fcW, fcb);
    fc_k<<<(BE * 32 + 255) / 256, 256>>>(y4, out);
}

// round 8
// speedup vs baseline: 1.5899x; 1.5899x over previous
#include <cuda_runtime.h>
#include <cuda_fp16.h>
#include <math.h>
#include <cstdint>

#define Bsz 32
#define Nn  100
#define Ee  9900
#define Hh  256
#define FIN 200
#define BE  (Bsz*Ee)    // 316800
#define BNr (Bsz*Nn)    // 3200
#define NCTA (BE/128)   // 2475

// ---------------- scratch (static device globals) ---------------------------
__device__ float g_h1[BNr*Hh];
__device__ float g_na[BNr*Hh];
__device__ float g_nb[BNr*Hh];
__device__ float g_as[BNr*Hh];
__device__ float g_ar[BNr*Hh];
__device__ __half g_xskipH[(size_t)BE*Hh];
__device__ __half g_preH[(size_t)BE*Hh];
__device__ float g_y4[(size_t)BE*Hh];
__device__ int   g_send[Ee];
__device__ int   g_recv[Ee];
__device__ float g_p3[(size_t)NCTA*256*2];   // per-CTA BN partials (sum, sumsq)
__device__ double g_chS[256], g_chQ[256];
__device__ float g_fcW[Hh*2];
__device__ float g_fcB[2];
// transposed fp16-split weight images: [n][k] layout, 3 mats
__device__ __half g_WtHi[3][65536];
__device__ __half g_WtLo[3][65536];

__device__ __forceinline__ float elu_f(float x) { return x > 0.f ? x : expm1f(x); }
__device__ __forceinline__ float elu_fast(float x) {
    float e = __expf(fminf(x, 0.f)) - 1.f;
    return x > 0.f ? x : e;
}

__device__ __forceinline__ uint32_t smem_u32(const void* p) {
    uint32_t a;
    asm("{ .reg .u64 t; cvta.to.shared.u64 t, %1; cvt.u32.u64 %0, t; }" : "=r"(a) : "l"(p));
    return a;
}
__device__ __forceinline__ uint32_t pack_h2(__half a, __half b) {
    __half2 h2 = __halves2half2(a, b);
    return *reinterpret_cast<uint32_t*>(&h2);
}

#define LDSM4(r, addr) \
    asm volatile("ldmatrix.sync.aligned.m8n8.x4.shared.b16 {%0,%1,%2,%3}, [%4];" \
        : "=r"((r)[0]), "=r"((r)[1]), "=r"((r)[2]), "=r"((r)[3]) : "r"(addr))

#define MMA16816(d, a, b0, b1) \
    asm volatile("mma.sync.aligned.m16n8k16.row.col.f32.f16.f16.f32 " \
        "{%0,%1,%2,%3},{%4,%5,%6,%7},{%8,%9},{%0,%1,%2,%3};" \
        : "+f"((d)[0]), "+f"((d)[1]), "+f"((d)[2]), "+f"((d)[3]) \
        : "r"((a)[0]), "r"((a)[1]), "r"((a)[2]), "r"((a)[3]), "r"(b0), "r"(b1))

#define CP16(dst, src) \
    asm volatile("cp.async.ca.shared.global [%0], [%1], 16;" :: "r"(dst), "l"(src))
#define CP_COMMIT() asm volatile("cp.async.commit_group;" ::: "memory")
#define CP_WAIT0()  asm volatile("cp.async.wait_group 0;" ::: "memory")

// ---------------- edge index extraction -------------------------------------
__global__ void build_idx_k(const float* __restrict__ rr, const float* __restrict__ rs) {
    int e = blockIdx.x * blockDim.x + threadIdx.x;
    if (e >= Ee) return;
    int r = 0, s = 0;
    for (int n = 0; n < Nn; n++) {
        if (rr[e*Nn + n] > 0.5f) r = n;
        if (rs[e*Nn + n] > 0.5f) s = n;
    }
    g_recv[e] = r;
    g_send[e] = s;
}

// ---------------- weight prep: transpose [k][n]->[n][k] + fp16 split --------
__global__ void prep_wt_k(const float* __restrict__ W,
                          __half* __restrict__ Hi, __half* __restrict__ Lo) {
    __shared__ float t[32][33];
    int k0 = blockIdx.x * 32, n0 = blockIdx.y * 32;
    int tx = threadIdx.x, ty = threadIdx.y;
    t[ty][tx] = W[(k0 + ty) * 256 + n0 + tx];
    __syncthreads();
    float v = t[tx][ty];
    __half h = __float2half_rn(v);
    __half l = __float2half_rn(v - __half2float(h));
    Hi[(n0 + ty) * 256 + k0 + tx] = h;
    Lo[(n0 + ty) * 256 + k0 + tx] = l;
}

// ---------------- big tensor-core GEMM: K64 chunks, double-buffered ---------
// CTA: 128 rows x 128 cols, K=256 in 4 chunks of 64, 2 CTAs/SM.
// AMODE 1: A = ELU(As[s]+Ar[r]+b1)            fp32 sources
// AMODE 2: A = ELU(preH + As[s]+Ar[r]+b1)     preH fp16
// AMODE 3: A = AmatH (fp16, direct cp.async)
// OUTF16:  store C as fp16 instead of fp32
#define ASTR  144
#define BHIOF 18432
#define BLOOF 36864
#define BUFSZ 55296
#define DSMEM (2*BUFSZ)   // 110592

template<int AMODE, int OUTF16>
__global__ __launch_bounds__(256, 2)
void gemm_tc(const __half* __restrict__ AmatH,
             const __half* __restrict__ WtHi, const __half* __restrict__ WtLo,
             const float* __restrict__ As_, const float* __restrict__ Ar_,
             const float* __restrict__ b1,
             const float* __restrict__ bias, int do_elu,
             void* __restrict__ Cout)
{
    extern __shared__ char sm[];
    __shared__ int sidx[128], ridx[128];

    const int tid  = threadIdx.x;
    const int lane = tid & 31, w = tid >> 5;
    const int row0 = blockIdx.x * 128;
    const int nbase = blockIdx.y * 128;
    const uint32_t sbase = smem_u32(sm);

    const int rowA  = tid >> 1;
    const int half0 = (tid & 1) * 32;
    const size_t arow = (size_t)(row0 + rowA) * 256;

    // B async copy for chunk cc into buffer bf (hi+lo, 128 rows x 128B each)
    #define CPB(cc, bf) do { \
        _Pragma("unroll") \
        for (int i = 0; i < 8; ++i) { \
            int seg = tid + i * 256; \
            int isLo = seg >> 10; \
            int rr = (seg >> 3) & 127; \
            int q  = seg & 7; \
            const __half* src = (isLo ? WtLo : WtHi) + (size_t)(nbase + rr) * 256 + (cc) * 64 + q * 8; \
            uint32_t dst = sbase + (bf) * BUFSZ + (isLo ? BLOOF : BHIOF) + rr * ASTR + q * 16; \
            CP16(dst, (const char*)src); \
        } \
    } while (0)

    // A async copy (AMODE 3 only): fp16 source, straight to smem
    #define CPA3(cc, bf) do { \
        _Pragma("unroll") \
        for (int i = 0; i < 4; ++i) { \
            int seg = tid + i * 256; \
            int rr = seg >> 3; \
            int q  = seg & 7; \
            const __half* src = AmatH + (size_t)(row0 + rr) * 256 + (cc) * 64 + q * 8; \
            uint32_t dst = sbase + (bf) * BUFSZ + rr * ASTR + q * 16; \
            CP16(dst, (const char*)src); \
        } \
    } while (0)

    // A build (AMODE 1/2): gather + combine + ELU + fp16 + STS
    #define STSA(cc, bf) do { \
        const int gk = (cc) * 64 + half0; \
        char* adst = sm + (bf) * BUFSZ + rowA * ASTR + half0 * 2; \
        _Pragma("unroll") \
        for (int it = 0; it < 4; ++it) { \
            int k0 = gk + it * 8; \
            float4 s0 = *(const float4*)(As_ + si + k0); \
            float4 s1 = *(const float4*)(As_ + si + k0 + 4); \
            float4 r0 = *(const float4*)(Ar_ + ri + k0); \
            float4 r1 = *(const float4*)(Ar_ + ri + k0 + 4); \
            float4 c0 = *(const float4*)(b1 + k0); \
            float4 c1 = *(const float4*)(b1 + k0 + 4); \
            float v0=s0.x+r0.x+c0.x, v1=s0.y+r0.y+c0.y, v2=s0.z+r0.z+c0.z, v3=s0.w+r0.w+c0.w; \
            float v4=s1.x+r1.x+c1.x, v5=s1.y+r1.y+c1.y, v6=s1.z+r1.z+c1.z, v7=s1.w+r1.w+c1.w; \
            if (AMODE == 2) { \
                uint4 pv = *(const uint4*)(AmatH + arow + k0); \
                float2 p0 = __half22float2(*(__half2*)&pv.x); \
                float2 p1 = __half22float2(*(__half2*)&pv.y); \
                float2 p2 = __half22float2(*(__half2*)&pv.z); \
                float2 p3 = __half22float2(*(__half2*)&pv.w); \
                v0+=p0.x; v1+=p0.y; v2+=p1.x; v3+=p1.y; \
                v4+=p2.x; v5+=p2.y; v6+=p3.x; v7+=p3.y; \
            } \
            v0=elu_fast(v0); v1=elu_fast(v1); v2=elu_fast(v2); v3=elu_fast(v3); \
            v4=elu_fast(v4); v5=elu_fast(v5); v6=elu_fast(v6); v7=elu_fast(v7); \
            uint4 o; \
            o.x = pack_h2(__float2half_rn(v0), __float2half_rn(v1)); \
            o.y = pack_h2(__float2half_rn(v2), __float2half_rn(v3)); \
            o.z = pack_h2(__float2half_rn(v4), __float2half_rn(v5)); \
            o.w = pack_h2(__float2half_rn(v6), __float2half_rn(v7)); \
            *(uint4*)(adst + it * 16) = o; \
        } \
    } while (0)

    // ---- prologue
    CPB(0, 0);
    if (AMODE == 3) CPA3(0, 0);
    CP_COMMIT();

    int si = 0, ri = 0;
    if (AMODE != 3) {
        if (tid < 128) {
            int row = row0 + tid;
            int b = row / Ee, e = row - b * Ee;
            sidx[tid] = (b * Nn + g_send[e]) * Hh;
            ridx[tid] = (b * Nn + g_recv[e]) * Hh;
        }
        __syncthreads();
        si = sidx[rowA]; ri = ridx[rowA];
        STSA(0, 0);
    }

    // ---- per-warp tile origin + ldmatrix lane addresses
    const int m0w = (w & 3) * 32;
    const int n0w = (w >> 2) * 64;
    const int laneA_row = (lane & 7) + ((lane >> 3) & 1) * 8;
    const int laneA_k   = ((lane >> 4) & 1) * 8;
    const int laneB_row = (lane & 7) + ((lane >> 4) & 1) * 8;
    const int laneB_k   = ((lane >> 3) & 1) * 8;

    uint32_t aOff[2], bOff[4];
    #pragma unroll
    for (int i = 0; i < 2; i++)
        aOff[i] = (uint32_t)((m0w + i*16 + laneA_row) * ASTR + laneA_k * 2);
    #pragma unroll
    for (int jp = 0; jp < 4; jp++)
        bOff[jp] = (uint32_t)(BHIOF + (n0w + jp*16 + laneB_row) * ASTR + laneB_k * 2);

    float acc[16][4];
    #pragma unroll
    for (int t = 0; t < 16; t++) { acc[t][0]=0.f; acc[t][1]=0.f; acc[t][2]=0.f; acc[t][3]=0.f; }

    // ---- mainloop: 4 chunks of K64
    #pragma unroll 1
    for (int c = 0; c < 4; ++c) {
        const int cur = c & 1, nxt = cur ^ 1;
        CP_WAIT0();
        __syncthreads();          // buf cur complete; buf nxt free
        if (c < 3) {
            CPB(c + 1, nxt);
            if (AMODE == 3) CPA3(c + 1, nxt);
            CP_COMMIT();
            if (AMODE != 3) STSA(c + 1, nxt);
        }
        const uint32_t base = sbase + cur * BUFSZ;
        #pragma unroll
        for (int ks = 0; ks < 4; ++ks) {
            uint32_t ah[2][4];
            #pragma unroll
            for (int i = 0; i < 2; i++)
                LDSM4(ah[i], base + aOff[i] + ks * 32);
            #pragma unroll
            for (int jp = 0; jp < 4; jp++) {
                uint32_t bh4[4], bl4[4];
                LDSM4(bh4, base + bOff[jp] + ks * 32);
                LDSM4(bl4, base + bOff[jp] + (BLOOF - BHIOF) + ks * 32);
                MMA16816(acc[0*8+2*jp],   ah[0], bh4[0], bh4[1]);
                MMA16816(acc[0*8+2*jp+1], ah[0], bh4[2], bh4[3]);
                MMA16816(acc[1*8+2*jp],   ah[1], bh4[0], bh4[1]);
                MMA16816(acc[1*8+2*jp+1], ah[1], bh4[2], bh4[3]);
                MMA16816(acc[0*8+2*jp],   ah[0], bl4[0], bl4[1]);
                MMA16816(acc[0*8+2*jp+1], ah[0], bl4[2], bl4[3]);
                MMA16816(acc[1*8+2*jp],   ah[1], bl4[0], bl4[1]);
                MMA16816(acc[1*8+2*jp+1], ah[1], bl4[2], bl4[3]);
            }
        }
    }

    // ---- epilogue
    const int g  = lane >> 2;
    const int tg = lane & 3;
    float cs[16], cq[16];
    if (AMODE == 2) {
        #pragma unroll
        for (int t = 0; t < 16; ++t) { cs[t] = 0.f; cq[t] = 0.f; }
    }
    float* Cf = (float*)Cout;
    __half* Ch = (__half*)Cout;
    #pragma unroll
    for (int i = 0; i < 2; i++) {
        #pragma unroll
        for (int j = 0; j < 8; j++) {
            int colg = nbase + n0w + j*8 + tg*2;
            float b0v = 0.f, b1v = 0.f;
            if (bias) { b0v = __ldg(bias + colg); b1v = __ldg(bias + colg + 1); }
            float* q = acc[i*8+j];
            int rlo = row0 + m0w + i*16 + g;
            int rhi = rlo + 8;
            float2 o0, o1;
            o0.x = q[0] + b0v; o0.y = q[1] + b1v;
            o1.x = q[2] + b0v; o1.y = q[3] + b1v;
            if (do_elu) {
                o0.x = elu_fast(o0.x); o0.y = elu_fast(o0.y);
                o1.x = elu_fast(o1.x); o1.y = elu_fast(o1.y);
            }
            if (AMODE == 2) {
                cs[j*2+0] += o0.x + o1.x;
                cs[j*2+1] += o0.y + o1.y;
                cq[j*2+0] += o0.x*o0.x + o1.x*o1.x;
                cq[j*2+1] += o0.y*o0.y + o1.y*o1.y;
            }
            if (OUTF16) {
                *(uint32_t*)(Ch + (size_t)rlo * 256 + colg) =
                    pack_h2(__float2half_rn(o0.x), __float2half_rn(o0.y));
                *(uint32_t*)(Ch + (size_t)rhi * 256 + colg) =
                    pack_h2(__float2half_rn(o1.x), __float2half_rn(o1.y));
            } else {
                *(float2*)(Cf + (size_t)rlo * 256 + colg) = o0;
                *(float2*)(Cf + (size_t)rhi * 256 + colg) = o1;
            }
        }
    }

    if (AMODE == 2) {
        #pragma unroll
        for (int t = 0; t < 16; ++t) {
            #pragma unroll
            for (int o = 4; o <= 16; o <<= 1) {
                cs[t] += __shfl_xor_sync(0xffffffffu, cs[t], o);
                cq[t] += __shfl_xor_sync(0xffffffffu, cq[t], o);
            }
        }
        __syncthreads();
        float* sps = (float*)sm;         // [8 warps][64 cols][2]
        if (lane < 4) {
            #pragma unroll
            for (int j = 0; j < 8; ++j) {
                #pragma unroll
                for (int par = 0; par < 2; ++par) {
                    int col = j*8 + lane*2 + par;
                    sps[(w*64 + col)*2 + 0] = cs[j*2+par];
                    sps[(w*64 + col)*2 + 1] = cq[j*2+par];
                }
            }
        }
        __syncthreads();
        int strip = tid >> 7, col = (tid >> 1) & 63, stat = tid & 1;
        float a2 = 0.f;
        #pragma unroll
        for (int wi = 0; wi < 4; ++wi)
            a2 += sps[((strip*4 + wi)*64 + col)*2 + stat];
        int ch = nbase + strip*64 + col;
        g_p3[((size_t)blockIdx.x * 256 + ch)*2 + stat] = a2;
    }
    #undef CPB
    #undef CPA3
    #undef STSA
}

// ---------------- small node-level SIMT GEMM (M=3200) -----------------------
__global__ __launch_bounds__(256)
void gemm_node(const float* __restrict__ A, int lda, int K,
               const float* __restrict__ W, const float* __restrict__ bias,
               int do_elu, float* __restrict__ C)
{
    __shared__ float sA[16][65];
    __shared__ float sB[16][64];
    const int row0 = blockIdx.x * 64;
    const int col0 = blockIdx.y * 64;
    const int tid  = threadIdx.x;
    const int ty   = tid >> 4, tx = tid & 15;
    float acc[4][4] = {};
    for (int kt = 0; kt < K; kt += 16) {
        #pragma unroll
        for (int i = 0; i < 4; i++) {
            int idx = tid + i * 256;
            int m = idx >> 4, k = idx & 15;
            int kk = kt + k;
            sA[k][m] = (kk < K) ? A[(size_t)(row0 + m) * lda + kk] : 0.f;
        }
        #pragma unroll
        for (int i = 0; i < 4; i++) {
            int idx = tid + i * 256;
            int k = idx >> 6, n = idx & 63;
            int kk = kt + k;
            sB[k][n] = (kk < K) ? W[(size_t)kk * 256 + col0 + n] : 0.f;
        }
        __syncthreads();
        #pragma unroll
        for (int k = 0; k < 16; k++) {
            float a[4], b[4];
            #pragma unroll
            for (int i = 0; i < 4; i++) a[i] = sA[k][ty*4 + i];
            #pragma unroll
            for (int j = 0; j < 4; j++) b[j] = sB[k][tx*4 + j];
            #pragma unroll
            for (int i = 0; i < 4; i++)
                #pragma unroll
                for (int j = 0; j < 4; j++)
                    acc[i][j] += a[i] * b[j];
        }
        __syncthreads();
    }
    #pragma unroll
    for (int i = 0; i < 4; i++) {
        int m = row0 + ty*4 + i;
        #pragma unroll
        for (int j = 0; j < 4; j++) {
            int n = col0 + tx*4 + j;
            float v = acc[i][j];
            if (bias) v += bias[n];
            if (do_elu) v = elu_f(v);
            C[(size_t)m * 256 + n] = v;
        }
    }
}

// ---------------- merged dual node GEMM: same A, two weight mats ------------
__global__ __launch_bounds__(256)
void gemm_node2(const float* __restrict__ A,
                const float* __restrict__ Wa, const float* __restrict__ Wb,
                float* __restrict__ Ca, float* __restrict__ Cb)
{
    const float* W = (blockIdx.y < 4) ? Wa : Wb;
    float* C       = (blockIdx.y < 4) ? Ca : Cb;
    const int col0 = (blockIdx.y & 3) * 64;
    __shared__ float sA[16][65];
    __shared__ float sB[16][64];
    const int row0 = blockIdx.x * 64;
    const int tid  = threadIdx.x;
    const int ty   = tid >> 4, tx = tid & 15;
    float acc[4][4] = {};
    for (int kt = 0; kt < 256; kt += 16) {
        #pragma unroll
        for (int i = 0; i < 4; i++) {
            int idx = tid + i * 256;
            int m = idx >> 4, k = idx & 15;
            sA[k][m] = A[(size_t)(row0 + m) * 256 + kt + k];
        }
        #pragma unroll
        for (int i = 0; i < 4; i++) {
            int idx = tid + i * 256;
            int k = idx >> 6, n = idx & 63;
            sB[k][n] = W[(size_t)(kt + k) * 256 + col0 + n];
        }
        __syncthreads();
        #pragma unroll
        for (int k = 0; k < 16; k++) {
            float a[4], b[4];
            #pragma unroll
            for (int i = 0; i < 4; i++) a[i] = sA[k][ty*4 + i];
            #pragma unroll
            for (int j = 0; j < 4; j++) b[j] = sB[k][tx*4 + j];
            #pragma unroll
            for (int i = 0; i < 4; i++)
                #pragma unroll
                for (int j = 0; j < 4; j++)
                    acc[i][j] += a[i] * b[j];
        }
        __syncthreads();
    }
    #pragma unroll
    for (int i = 0; i < 4; i++) {
        int m = row0 + ty*4 + i;
        #pragma unroll
        for (int j = 0; j < 4; j++)
            C[(size_t)m * 256 + col0 + tx*4 + j] = acc[i][j];
    }
}

// ---------------- edge2node: contiguous 99-edge segment mean (fp16 in) ------
__global__ void edge2node_k(const __half* __restrict__ x, float* __restrict__ out) {
    int nodeRow = blockIdx.x;
    int h = threadIdx.x;
    int b = nodeRow / Nn, n = nodeRow - b * Nn;
    const __half* base = x + (size_t)(b * Ee + n * 99) * Hh + h;
    float s = 0.f;
    #pragma unroll 3
    for (int r = 0; r < 99; r++) s += __half2float(base[(size_t)r * Hh]);
    out[(size_t)nodeRow * Hh + h] = s * (1.0f / 9900.0f);
}

// ---------------- BN partial reduce: parallel deterministic tree ------------
__global__ void bn_reduce_k() {
    int ch = blockIdx.x, t = threadIdx.x;
    double s = 0.0, q = 0.0;
    for (int bx = t; bx < NCTA; bx += 256) {
        s += (double)g_p3[((size_t)bx * 256 + ch) * 2 + 0];
        q += (double)g_p3[((size_t)bx * 256 + ch) * 2 + 1];
    }
    __shared__ double ss[256], sq[256];
    ss[t] = s; sq[t] = q;
    __syncthreads();
    for (int st = 128; st > 0; st >>= 1) {
        if (t < st) { ss[t] += ss[t + st]; sq[t] += sq[t + st]; }
        __syncthreads();
    }
    if (t == 0) { g_chS[ch] = ss[0]; g_chQ[ch] = sq[0]; }
}

// ---------------- BN finalize + fold into fc --------------------------------
__global__ void bn_fin3(const float* __restrict__ gamma, const float* __restrict__ beta,
                        const float* __restrict__ W, const float* __restrict__ fb) {
    int ch = threadIdx.x;
    double s = g_chS[ch], q = g_chQ[ch];
    double m = s / (double)BE;
    double v = q / (double)BE - m * m;
    float sc = (float)(rsqrt(v + 1e-5) * (double)gamma[ch]);
    float sh = beta[ch] - (float)m * sc;
    float w0 = W[ch*2 + 0], w1 = W[ch*2 + 1];
    g_fcW[ch*2 + 0] = sc * w0;
    g_fcW[ch*2 + 1] = sc * w1;
    __shared__ float r0s[256], r1s[256];
    r0s[ch] = sh * w0;
    r1s[ch] = sh * w1;
    __syncthreads();
    for (int st = 128; st > 0; st >>= 1) {
        if (ch < st) { r0s[ch] += r0s[ch + st]; r1s[ch] += r1s[ch + st]; }
        __syncthreads();
    }
    if (ch == 0) { g_fcB[0] = r0s[0] + fb[0]; g_fcB[1] = r1s[0] + fb[1]; }
}

// ---------------- final fc (folded BN): warp per row ------------------------
__global__ void fc_k(const float* __restrict__ y, float* __restrict__ out) {
    int gwarp = (blockIdx.x * blockDim.x + threadIdx.x) >> 5;
    int lane  = threadIdx.x & 31;
    if (gwarp >= BE) return;
    const float* row = y + (size_t)gwarp * Hh;
    float a0 = 0.f, a1 = 0.f;
    #pragma unroll
    for (int i = lane; i < Hh; i += 32) {
        float v = row[i];
        a0 += v * g_fcW[i*2 + 0];
        a1 += v * g_fcW[i*2 + 1];
    }
    #pragma unroll
    for (int o = 16; o > 0; o >>= 1) {
        a0 += __shfl_down_sync(0xffffffffu, a0, o);
        a1 += __shfl_down_sync(0xffffffffu, a1, o);
    }
    if (lane == 0) {
        out[(size_t)gwarp * 2 + 0] = a0 + g_fcB[0];
        out[(size_t)gwarp * 2 + 1] = a1 + g_fcB[1];
    }
}

// ---------------------------------------------------------------------------
extern "C" void kernel_launch(void* const* d_in, const int* in_sizes, int n_in,
                              void* d_out, int out_size) {
    const float* inputs  = (const float*)d_in[0];
    const float* rel_rec = (const float*)d_in[1];
    const float* rel_snd = (const float*)d_in[2];
    const float* m1W1 = (const float*)d_in[3];  const float* m1b1 = (const float*)d_in[4];
    const float* m1W2 = (const float*)d_in[5];  const float* m1b2 = (const float*)d_in[6];
    const float* m2W1 = (const float*)d_in[7];  const float* m2b1 = (const float*)d_in[8];
    const float* m2W2 = (const float*)d_in[9];  const float* m2b2 = (const float*)d_in[10];
    const float* m3W1 = (const float*)d_in[11]; const float* m3b1 = (const float*)d_in[12];
    const float* m3W2 = (const float*)d_in[13]; const float* m3b2 = (const float*)d_in[14];
    const float* m4W1 = (const float*)d_in[15]; const float* m4b1 = (const float*)d_in[16];
    const float* m4W2 = (const float*)d_in[17]; const float* m4b2 = (const float*)d_in[18];
    const float* gmma = (const float*)d_in[19]; const float* beta = (const float*)d_in[20];
    const float* fcW  = (const float*)d_in[21]; const float* fcb  = (const float*)d_in[22];
    float* out = (float*)d_out;

    float *h1, *na, *nb, *as_, *ar_, *y4;
    __half *xskipH, *preH, *wth, *wtl;
    cudaGetSymbolAddress((void**)&h1, g_h1);
    cudaGetSymbolAddress((void**)&na, g_na);
    cudaGetSymbolAddress((void**)&nb, g_nb);
    cudaGetSymbolAddress((void**)&as_, g_as);
    cudaGetSymbolAddress((void**)&ar_, g_ar);
    cudaGetSymbolAddress((void**)&xskipH, g_xskipH);
    cudaGetSymbolAddress((void**)&preH, g_preH);
    cudaGetSymbolAddress((void**)&y4, g_y4);
    cudaGetSymbolAddress((void**)&wth, g_WtHi);
    cudaGetSymbolAddress((void**)&wtl, g_WtLo);

    cudaFuncSetAttribute((const void*)gemm_tc<1,1>, cudaFuncAttributeMaxDynamicSharedMemorySize, DSMEM);
    cudaFuncSetAttribute((const void*)gemm_tc<3,1>, cudaFuncAttributeMaxDynamicSharedMemorySize, DSMEM);
    cudaFuncSetAttribute((const void*)gemm_tc<2,0>, cudaFuncAttributeMaxDynamicSharedMemorySize, DSMEM);

    dim3 gN(BNr / 64, 4);
    dim3 gN2(BNr / 64, 8);
    dim3 gE(NCTA, 2);
    dim3 tb(32, 32);
    dim3 tg(8, 8);

    // edge index tables + weight prep (transpose + fp16 split)
    build_idx_k<<<(Ee + 127) / 128, 128>>>(rel_rec, rel_snd);
    prep_wt_k<<<tg, tb>>>(m2W2,             wth + 0 * 65536, wtl + 0 * 65536);
    prep_wt_k<<<tg, tb>>>(m4W1 + 512 * 256, wth + 1 * 65536, wtl + 1 * 65536);
    prep_wt_k<<<tg, tb>>>(m4W2,             wth + 2 * 65536, wtl + 2 * 65536);

    // mlp1 (node level)
    gemm_node<<<gN, 256>>>(inputs, FIN, FIN, m1W1, m1b1, 1, na);
    gemm_node<<<gN, 256>>>(na, Hh, Hh, m1W2, m1b2, 1, h1);

    // node projections for mlp2 layer1 (send + recv halves, one launch)
    gemm_node2<<<gN2, 256>>>(h1, m2W1, m2W1 + 256*256, as_, ar_);

    // big GEMM #1: xskipH = fp16( ELU(ELU(as[s]+ar[r]+b1) @ W2 + b2) )
    gemm_tc<1,1><<<gE, 256, DSMEM>>>(nullptr, wth + 0 * 65536, wtl + 0 * 65536,
                                     as_, ar_, m2b1, m2b2, 1, xskipH);

    // edge2node + mlp3 (node level)
    edge2node_k<<<BNr, 256>>>(xskipH, na);
    gemm_node<<<gN, 256>>>(na, Hh, Hh, m3W1, m3b1, 1, nb);
    gemm_node<<<gN, 256>>>(nb, Hh, Hh, m3W2, m3b2, 1, h1);

    // node projections for mlp4 layer1
    gemm_node2<<<gN2, 256>>>(h1, m4W1, m4W1 + 256*256, as_, ar_);

    // big GEMM #2: preH = fp16( xskipH @ W4_1[512:768] )   (pure cp.async A)
    gemm_tc<3,1><<<gE, 256, DSMEM>>>(xskipH, wth + 1 * 65536, wtl + 1 * 65536,
                                     nullptr, nullptr, nullptr, nullptr, 0, preH);

    // big GEMM #3: y4 = ELU(ELU(preH + as[s]+ar[r]+b1) @ W4_2 + b2) + BN partials
    gemm_tc<2,0><<<gE, 256, DSMEM>>>(preH, wth + 2 * 65536, wtl + 2 * 65536,
                                     as_, ar_, m4b1, m4b2, 1, y4);

    // BN reduce (parallel deterministic), finalize, final fc
    bn_reduce_k<<<256, 256>>>();
    bn_fin3<<<1, 256>>>(gmma, beta, fcW, fcb);
    fc_k<<<(BE * 32 + 255) / 256, 256>>>(y4, out);
}

// round 9
// speedup vs baseline: 1.6931x; 1.0649x over previous
#include <cuda_runtime.h>
#include <cuda_fp16.h>
#include <math.h>
#include <cstdint>

#define Bsz 32
#define Nn  100
#define Ee  9900
#define Hh  256
#define FIN 200
#define BE  (Bsz*Ee)    // 316800
#define BNr (Bsz*Nn)    // 3200
#define NCTA (BE/128)   // 2475

// ---------------- scratch (static device globals) ---------------------------
__device__ float g_h1[BNr*Hh];
__device__ float g_na[BNr*Hh];
__device__ float g_nb[BNr*Hh];
__device__ float g_as[BNr*Hh];
__device__ float g_ar[BNr*Hh];
__device__ __half g_xskipH[(size_t)BE*Hh];
__device__ __half g_preH[(size_t)BE*Hh];
__device__ __half g_y4H[(size_t)BE*Hh];
__device__ int   g_send[Ee];
__device__ int   g_recv[Ee];
__device__ float g_p3[(size_t)NCTA*256*2];   // per-CTA BN partials (sum, sumsq)
__device__ double g_chS[256], g_chQ[256];
__device__ float g_fcW[Hh*2];
__device__ float g_fcB[2];
// transposed fp16-split weight images: [n][k] layout, 3 mats
__device__ __half g_WtHi[3][65536];
__device__ __half g_WtLo[3][65536];

__device__ __forceinline__ float elu_f(float x) { return x > 0.f ? x : expm1f(x); }
__device__ __forceinline__ float elu_fast(float x) {
    float e = __expf(fminf(x, 0.f)) - 1.f;
    return x > 0.f ? x : e;
}

__device__ __forceinline__ uint32_t smem_u32(const void* p) {
    uint32_t a;
    asm("{ .reg .u64 t; cvta.to.shared.u64 t, %1; cvt.u32.u64 %0, t; }" : "=r"(a) : "l"(p));
    return a;
}
__device__ __forceinline__ uint32_t pack_h2(__half a, __half b) {
    __half2 h2 = __halves2half2(a, b);
    return *reinterpret_cast<uint32_t*>(&h2);
}

#define LDSM4(r, addr) \
    asm volatile("ldmatrix.sync.aligned.m8n8.x4.shared.b16 {%0,%1,%2,%3}, [%4];" \
        : "=r"((r)[0]), "=r"((r)[1]), "=r"((r)[2]), "=r"((r)[3]) : "r"(addr))

#define MMA16816(d, a, b0, b1) \
    asm volatile("mma.sync.aligned.m16n8k16.row.col.f32.f16.f16.f32 " \
        "{%0,%1,%2,%3},{%4,%5,%6,%7},{%8,%9},{%0,%1,%2,%3};" \
        : "+f"((d)[0]), "+f"((d)[1]), "+f"((d)[2]), "+f"((d)[3]) \
        : "r"((a)[0]), "r"((a)[1]), "r"((a)[2]), "r"((a)[3]), "r"(b0), "r"(b1))

#define CP16(dst, src) \
    asm volatile("cp.async.ca.shared.global [%0], [%1], 16;" :: "r"(dst), "l"(src))
#define CP_COMMIT() asm volatile("cp.async.commit_group;" ::: "memory")
#define CP_WAIT0()  asm volatile("cp.async.wait_group 0;" ::: "memory")

// ---------------- edge index extraction -------------------------------------
__global__ void build_idx_k(const float* __restrict__ rr, const float* __restrict__ rs) {
    int e = blockIdx.x * blockDim.x + threadIdx.x;
    if (e >= Ee) return;
    int r = 0, s = 0;
    for (int n = 0; n < Nn; n++) {
        if (rr[e*Nn + n] > 0.5f) r = n;
        if (rs[e*Nn + n] > 0.5f) s = n;
    }
    g_recv[e] = r;
    g_send[e] = s;
}

// ---------------- weight prep: transpose [k][n]->[n][k] + fp16 split --------
__global__ void prep_wt_k(const float* __restrict__ W,
                          __half* __restrict__ Hi, __half* __restrict__ Lo) {
    __shared__ float t[32][33];
    int k0 = blockIdx.x * 32, n0 = blockIdx.y * 32;
    int tx = threadIdx.x, ty = threadIdx.y;
    t[ty][tx] = W[(k0 + ty) * 256 + n0 + tx];
    __syncthreads();
    float v = t[tx][ty];
    __half h = __float2half_rn(v);
    __half l = __float2half_rn(v - __half2float(h));
    Hi[(n0 + ty) * 256 + k0 + tx] = h;
    Lo[(n0 + ty) * 256 + k0 + tx] = l;
}

// ---------------- big tensor-core GEMM: K64 chunks, double-buffered ---------
// CTA: 128 rows x 128 cols, K=256 in 4 chunks of 64, 2 CTAs/SM.
// AMODE 1: A = ELU(As[s]+Ar[r]+b1)            fp32 sources
// AMODE 2: A = ELU(preH + As[s]+Ar[r]+b1)     preH fp16
// AMODE 3: A = AmatH (fp16, direct cp.async)
// OUTF16:  store C as fp16 instead of fp32
// WTERMS:  1 = hi-only weights (half MMA), 2 = hi+lo split
#define ASTR  144
#define BHIOF 18432
#define BLOOF 36864
#define BUFSZ 55296
#define DSMEM (2*BUFSZ)   // 110592

template<int AMODE, int OUTF16, int WTERMS>
__global__ __launch_bounds__(256, 2)
void gemm_tc(const __half* __restrict__ AmatH,
             const __half* __restrict__ WtHi, const __half* __restrict__ WtLo,
             const float* __restrict__ As_, const float* __restrict__ Ar_,
             const float* __restrict__ b1,
             const float* __restrict__ bias, int do_elu,
             void* __restrict__ Cout)
{
    extern __shared__ char sm[];
    __shared__ int sidx[128], ridx[128];

    const int tid  = threadIdx.x;
    const int lane = tid & 31, w = tid >> 5;
    const int row0 = blockIdx.x * 128;
    const int nbase = blockIdx.y * 128;
    const uint32_t sbase = smem_u32(sm);

    const int rowA  = tid >> 1;
    const int half0 = (tid & 1) * 32;
    const size_t arow = (size_t)(row0 + rowA) * 256;

    // B async copy for chunk cc into buffer bf (hi [+ lo], 128 rows x 128B each)
    #define CPB(cc, bf) do { \
        _Pragma("unroll") \
        for (int i = 0; i < WTERMS * 4; ++i) { \
            int seg = tid + i * 256; \
            int isLo = seg >> 10; \
            int rr = (seg >> 3) & 127; \
            int q  = seg & 7; \
            const __half* src = (isLo ? WtLo : WtHi) + (size_t)(nbase + rr) * 256 + (cc) * 64 + q * 8; \
            uint32_t dst = sbase + (bf) * BUFSZ + (isLo ? BLOOF : BHIOF) + rr * ASTR + q * 16; \
            CP16(dst, (const char*)src); \
        } \
    } while (0)

    // A async copy (AMODE 3 only): fp16 source, straight to smem
    #define CPA3(cc, bf) do { \
        _Pragma("unroll") \
        for (int i = 0; i < 4; ++i) { \
            int seg = tid + i * 256; \
            int rr = seg >> 3; \
            int q  = seg & 7; \
            const __half* src = AmatH + (size_t)(row0 + rr) * 256 + (cc) * 64 + q * 8; \
            uint32_t dst = sbase + (bf) * BUFSZ + rr * ASTR + q * 16; \
            CP16(dst, (const char*)src); \
        } \
    } while (0)

    // A build (AMODE 1/2): gather + combine + ELU + fp16 + STS
    #define STSA(cc, bf) do { \
        const int gk = (cc) * 64 + half0; \
        char* adst = sm + (bf) * BUFSZ + rowA * ASTR + half0 * 2; \
        _Pragma("unroll") \
        for (int it = 0; it < 4; ++it) { \
            int k0 = gk + it * 8; \
            float4 s0 = *(const float4*)(As_ + si + k0); \
            float4 s1 = *(const float4*)(As_ + si + k0 + 4); \
            float4 r0 = *(const float4*)(Ar_ + ri + k0); \
            float4 r1 = *(const float4*)(Ar_ + ri + k0 + 4); \
            float4 c0 = *(const float4*)(b1 + k0); \
            float4 c1 = *(const float4*)(b1 + k0 + 4); \
            float v0=s0.x+r0.x+c0.x, v1=s0.y+r0.y+c0.y, v2=s0.z+r0.z+c0.z, v3=s0.w+r0.w+c0.w; \
            float v4=s1.x+r1.x+c1.x, v5=s1.y+r1.y+c1.y, v6=s1.z+r1.z+c1.z, v7=s1.w+r1.w+c1.w; \
            if (AMODE == 2) { \
                uint4 pv = *(const uint4*)(AmatH + arow + k0); \
                float2 p0 = __half22float2(*(__half2*)&pv.x); \
                float2 p1 = __half22float2(*(__half2*)&pv.y); \
                float2 p2 = __half22float2(*(__half2*)&pv.z); \
                float2 p3 = __half22float2(*(__half2*)&pv.w); \
                v0+=p0.x; v1+=p0.y; v2+=p1.x; v3+=p1.y; \
                v4+=p2.x; v5+=p2.y; v6+=p3.x; v7+=p3.y; \
            } \
            v0=elu_fast(v0); v1=elu_fast(v1); v2=elu_fast(v2); v3=elu_fast(v3); \
            v4=elu_fast(v4); v5=elu_fast(v5); v6=elu_fast(v6); v7=elu_fast(v7); \
            uint4 o; \
            o.x = pack_h2(__float2half_rn(v0), __float2half_rn(v1)); \
            o.y = pack_h2(__float2half_rn(v2), __float2half_rn(v3)); \
            o.z = pack_h2(__float2half_rn(v4), __float2half_rn(v5)); \
            o.w = pack_h2(__float2half_rn(v6), __float2half_rn(v7)); \
            *(uint4*)(adst + it * 16) = o; \
        } \
    } while (0)

    // ---- prologue
    CPB(0, 0);
    if (AMODE == 3) CPA3(0, 0);
    CP_COMMIT();

    int si = 0, ri = 0;
    if (AMODE != 3) {
        if (tid < 128) {
            int row = row0 + tid;
            int b = row / Ee, e = row - b * Ee;
            sidx[tid] = (b * Nn + g_send[e]) * Hh;
            ridx[tid] = (b * Nn + g_recv[e]) * Hh;
        }
        __syncthreads();
        si = sidx[rowA]; ri = ridx[rowA];
        STSA(0, 0);
    }

    // ---- per-warp tile origin + ldmatrix lane addresses
    const int m0w = (w & 3) * 32;
    const int n0w = (w >> 2) * 64;
    const int laneA_row = (lane & 7) + ((lane >> 3) & 1) * 8;
    const int laneA_k   = ((lane >> 4) & 1) * 8;
    const int laneB_row = (lane & 7) + ((lane >> 4) & 1) * 8;
    const int laneB_k   = ((lane >> 3) & 1) * 8;

    uint32_t aOff[2], bOff[4];
    #pragma unroll
    for (int i = 0; i < 2; i++)
        aOff[i] = (uint32_t)((m0w + i*16 + laneA_row) * ASTR + laneA_k * 2);
    #pragma unroll
    for (int jp = 0; jp < 4; jp++)
        bOff[jp] = (uint32_t)(BHIOF + (n0w + jp*16 + laneB_row) * ASTR + laneB_k * 2);

    float acc[16][4];
    #pragma unroll
    for (int t = 0; t < 16; t++) { acc[t][0]=0.f; acc[t][1]=0.f; acc[t][2]=0.f; acc[t][3]=0.f; }

    // ---- mainloop: 4 chunks of K64
    #pragma unroll 1
    for (int c = 0; c < 4; ++c) {
        const int cur = c & 1, nxt = cur ^ 1;
        CP_WAIT0();
        __syncthreads();          // buf cur complete; buf nxt free
        if (c < 3) {
            CPB(c + 1, nxt);
            if (AMODE == 3) CPA3(c + 1, nxt);
            CP_COMMIT();
            if (AMODE != 3) STSA(c + 1, nxt);
        }
        const uint32_t base = sbase + cur * BUFSZ;
        #pragma unroll
        for (int ks = 0; ks < 4; ++ks) {
            uint32_t ah[2][4];
            #pragma unroll
            for (int i = 0; i < 2; i++)
                LDSM4(ah[i], base + aOff[i] + ks * 32);
            #pragma unroll
            for (int jp = 0; jp < 4; jp++) {
                uint32_t bh4[4];
                LDSM4(bh4, base + bOff[jp] + ks * 32);
                MMA16816(acc[0*8+2*jp],   ah[0], bh4[0], bh4[1]);
                MMA16816(acc[0*8+2*jp+1], ah[0], bh4[2], bh4[3]);
                MMA16816(acc[1*8+2*jp],   ah[1], bh4[0], bh4[1]);
                MMA16816(acc[1*8+2*jp+1], ah[1], bh4[2], bh4[3]);
                if (WTERMS == 2) {
                    uint32_t bl4[4];
                    LDSM4(bl4, base + bOff[jp] + (BLOOF - BHIOF) + ks * 32);
                    MMA16816(acc[0*8+2*jp],   ah[0], bl4[0], bl4[1]);
                    MMA16816(acc[0*8+2*jp+1], ah[0], bl4[2], bl4[3]);
                    MMA16816(acc[1*8+2*jp],   ah[1], bl4[0], bl4[1]);
                    MMA16816(acc[1*8+2*jp+1], ah[1], bl4[2], bl4[3]);
                }
            }
        }
    }

    // ---- epilogue
    const int g  = lane >> 2;
    const int tg = lane & 3;
    float cs[16], cq[16];
    if (AMODE == 2) {
        #pragma unroll
        for (int t = 0; t < 16; ++t) { cs[t] = 0.f; cq[t] = 0.f; }
    }
    float* Cf = (float*)Cout;
    __half* Ch = (__half*)Cout;
    #pragma unroll
    for (int i = 0; i < 2; i++) {
        #pragma unroll
        for (int j = 0; j < 8; j++) {
            int colg = nbase + n0w + j*8 + tg*2;
            float b0v = 0.f, b1v = 0.f;
            if (bias) { b0v = __ldg(bias + colg); b1v = __ldg(bias + colg + 1); }
            float* q = acc[i*8+j];
            int rlo = row0 + m0w + i*16 + g;
            int rhi = rlo + 8;
            float2 o0, o1;
            o0.x = q[0] + b0v; o0.y = q[1] + b1v;
            o1.x = q[2] + b0v; o1.y = q[3] + b1v;
            if (do_elu) {
                o0.x = elu_fast(o0.x); o0.y = elu_fast(o0.y);
                o1.x = elu_fast(o1.x); o1.y = elu_fast(o1.y);
            }
            if (AMODE == 2) {
                cs[j*2+0] += o0.x + o1.x;
                cs[j*2+1] += o0.y + o1.y;
                cq[j*2+0] += o0.x*o0.x + o1.x*o1.x;
                cq[j*2+1] += o0.y*o0.y + o1.y*o1.y;
            }
            if (OUTF16) {
                *(uint32_t*)(Ch + (size_t)rlo * 256 + colg) =
                    pack_h2(__float2half_rn(o0.x), __float2half_rn(o0.y));
                *(uint32_t*)(Ch + (size_t)rhi * 256 + colg) =
                    pack_h2(__float2half_rn(o1.x), __float2half_rn(o1.y));
            } else {
                *(float2*)(Cf + (size_t)rlo * 256 + colg) = o0;
                *(float2*)(Cf + (size_t)rhi * 256 + colg) = o1;
            }
        }
    }

    if (AMODE == 2) {
        #pragma unroll
        for (int t = 0; t < 16; ++t) {
            #pragma unroll
            for (int o = 4; o <= 16; o <<= 1) {
                cs[t] += __shfl_xor_sync(0xffffffffu, cs[t], o);
                cq[t] += __shfl_xor_sync(0xffffffffu, cq[t], o);
            }
        }
        __syncthreads();
        float* sps = (float*)sm;         // [8 warps][64 cols][2]
        if (lane < 4) {
            #pragma unroll
            for (int j = 0; j < 8; ++j) {
                #pragma unroll
                for (int par = 0; par < 2; ++par) {
                    int col = j*8 + lane*2 + par;
                    sps[(w*64 + col)*2 + 0] = cs[j*2+par];
                    sps[(w*64 + col)*2 + 1] = cq[j*2+par];
                }
            }
        }
        __syncthreads();
        int strip = tid >> 7, col = (tid >> 1) & 63, stat = tid & 1;
        float a2 = 0.f;
        #pragma unroll
        for (int wi = 0; wi < 4; ++wi)
            a2 += sps[((strip*4 + wi)*64 + col)*2 + stat];
        int ch = nbase + strip*64 + col;
        g_p3[((size_t)blockIdx.x * 256 + ch)*2 + stat] = a2;
    }
    #undef CPB
    #undef CPA3
    #undef STSA
}

// ---------------- small node-level SIMT GEMM (M=3200) -----------------------
__global__ __launch_bounds__(256)
void gemm_node(const float* __restrict__ A, int lda, int K,
               const float* __restrict__ W, const float* __restrict__ bias,
               int do_elu, float* __restrict__ C)
{
    __shared__ float sA[16][65];
    __shared__ float sB[16][64];
    const int row0 = blockIdx.x * 64;
    const int col0 = blockIdx.y * 64;
    const int tid  = threadIdx.x;
    const int ty   = tid >> 4, tx = tid & 15;
    float acc[4][4] = {};
    for (int kt = 0; kt < K; kt += 16) {
        #pragma unroll
        for (int i = 0; i < 4; i++) {
            int idx = tid + i * 256;
            int m = idx >> 4, k = idx & 15;
            int kk = kt + k;
            sA[k][m] = (kk < K) ? A[(size_t)(row0 + m) * lda + kk] : 0.f;
        }
        #pragma unroll
        for (int i = 0; i < 4; i++) {
            int idx = tid + i * 256;
            int k = idx >> 6, n = idx & 63;
            int kk = kt + k;
            sB[k][n] = (kk < K) ? W[(size_t)kk * 256 + col0 + n] : 0.f;
        }
        __syncthreads();
        #pragma unroll
        for (int k = 0; k < 16; k++) {
            float a[4], b[4];
            #pragma unroll
            for (int i = 0; i < 4; i++) a[i] = sA[k][ty*4 + i];
            #pragma unroll
            for (int j = 0; j < 4; j++) b[j] = sB[k][tx*4 + j];
            #pragma unroll
            for (int i = 0; i < 4; i++)
                #pragma unroll
                for (int j = 0; j < 4; j++)
                    acc[i][j] += a[i] * b[j];
        }
        __syncthreads();
    }
    #pragma unroll
    for (int i = 0; i < 4; i++) {
        int m = row0 + ty*4 + i;
        #pragma unroll
        for (int j = 0; j < 4; j++) {
            int n = col0 + tx*4 + j;
            float v = acc[i][j];
            if (bias) v += bias[n];
            if (do_elu) v = elu_f(v);
            C[(size_t)m * 256 + n] = v;
        }
    }
}

// ---------------- merged dual node GEMM: same A, two weight mats ------------
__global__ __launch_bounds__(256)
void gemm_node2(const float* __restrict__ A,
                const float* __restrict__ Wa, const float* __restrict__ Wb,
                float* __restrict__ Ca, float* __restrict__ Cb)
{
    const float* W = (blockIdx.y < 4) ? Wa : Wb;
    float* C       = (blockIdx.y < 4) ? Ca : Cb;
    const int col0 = (blockIdx.y & 3) * 64;
    __shared__ float sA[16][65];
    __shared__ float sB[16][64];
    const int row0 = blockIdx.x * 64;
    const int tid  = threadIdx.x;
    const int ty   = tid >> 4, tx = tid & 15;
    float acc[4][4] = {};
    for (int kt = 0; kt < 256; kt += 16) {
        #pragma unroll
        for (int i = 0; i < 4; i++) {
            int idx = tid + i * 256;
            int m = idx >> 4, k = idx & 15;
            sA[k][m] = A[(size_t)(row0 + m) * 256 + kt + k];
        }
        #pragma unroll
        for (int i = 0; i < 4; i++) {
            int idx = tid + i * 256;
            int k = idx >> 6, n = idx & 63;
            sB[k][n] = W[(size_t)(kt + k) * 256 + col0 + n];
        }
        __syncthreads();
        #pragma unroll
        for (int k = 0; k < 16; k++) {
            float a[4], b[4];
            #pragma unroll
            for (int i = 0; i < 4; i++) a[i] = sA[k][ty*4 + i];
            #pragma unroll
            for (int j = 0; j < 4; j++) b[j] = sB[k][tx*4 + j];
            #pragma unroll
            for (int i = 0; i < 4; i++)
                #pragma unroll
                for (int j = 0; j < 4; j++)
                    acc[i][j] += a[i] * b[j];
        }
        __syncthreads();
    }
    #pragma unroll
    for (int i = 0; i < 4; i++) {
        int m = row0 + ty*4 + i;
        #pragma unroll
        for (int j = 0; j < 4; j++)
            C[(size_t)m * 256 + col0 + tx*4 + j] = acc[i][j];
    }
}

// ---------------- edge2node: contiguous 99-edge segment mean (fp16 in) ------
__global__ void edge2node_k(const __half* __restrict__ x, float* __restrict__ out) {
    int nodeRow = blockIdx.x;
    int h = threadIdx.x;
    int b = nodeRow / Nn, n = nodeRow - b * Nn;
    const __half* base = x + (size_t)(b * Ee + n * 99) * Hh + h;
    float s = 0.f;
    #pragma unroll 3
    for (int r = 0; r < 99; r++) s += __half2float(base[(size_t)r * Hh]);
    out[(size_t)nodeRow * Hh + h] = s * (1.0f / 9900.0f);
}

// ---------------- BN partial reduce: parallel deterministic tree ------------
__global__ void bn_reduce_k() {
    int ch = blockIdx.x, t = threadIdx.x;
    double s = 0.0, q = 0.0;
    for (int bx = t; bx < NCTA; bx += 256) {
        s += (double)g_p3[((size_t)bx * 256 + ch) * 2 + 0];
        q += (double)g_p3[((size_t)bx * 256 + ch) * 2 + 1];
    }
    __shared__ double ss[256], sq[256];
    ss[t] = s; sq[t] = q;
    __syncthreads();
    for (int st = 128; st > 0; st >>= 1) {
        if (t < st) { ss[t] += ss[t + st]; sq[t] += sq[t + st]; }
        __syncthreads();
    }
    if (t == 0) { g_chS[ch] = ss[0]; g_chQ[ch] = sq[0]; }
}

// ---------------- BN finalize + fold into fc --------------------------------
__global__ void bn_fin3(const float* __restrict__ gamma, const float* __restrict__ beta,
                        const float* __restrict__ W, const float* __restrict__ fb) {
    int ch = threadIdx.x;
    double s = g_chS[ch], q = g_chQ[ch];
    double m = s / (double)BE;
    double v = q / (double)BE - m * m;
    float sc = (float)(rsqrt(v + 1e-5) * (double)gamma[ch]);
    float sh = beta[ch] - (float)m * sc;
    float w0 = W[ch*2 + 0], w1 = W[ch*2 + 1];
    g_fcW[ch*2 + 0] = sc * w0;
    g_fcW[ch*2 + 1] = sc * w1;
    __shared__ float r0s[256], r1s[256];
    r0s[ch] = sh * w0;
    r1s[ch] = sh * w1;
    __syncthreads();
    for (int st = 128; st > 0; st >>= 1) {
        if (ch < st) { r0s[ch] += r0s[ch + st]; r1s[ch] += r1s[ch + st]; }
        __syncthreads();
    }
    if (ch == 0) { g_fcB[0] = r0s[0] + fb[0]; g_fcB[1] = r1s[0] + fb[1]; }
}

// ---------------- final fc (folded BN): warp per row, fp16 y ----------------
__global__ void fc_k(const __half* __restrict__ y, float* __restrict__ out) {
    int gwarp = (blockIdx.x * blockDim.x + threadIdx.x) >> 5;
    int lane  = threadIdx.x & 31;
    if (gwarp >= BE) return;
    const __half2* row = (const __half2*)(y + (size_t)gwarp * Hh);
    float a0 = 0.f, a1 = 0.f;
    #pragma unroll
    for (int i = lane; i < 128; i += 32) {
        float2 v = __half22float2(row[i]);
        int ch = i * 2;
        a0 += v.x * g_fcW[ch*2 + 0] + v.y * g_fcW[ch*2 + 2];
        a1 += v.x * g_fcW[ch*2 + 1] + v.y * g_fcW[ch*2 + 3];
    }
    #pragma unroll
    for (int o = 16; o > 0; o >>= 1) {
        a0 += __shfl_down_sync(0xffffffffu, a0, o);
        a1 += __shfl_down_sync(0xffffffffu, a1, o);
    }
    if (lane == 0) {
        out[(size_t)gwarp * 2 + 0] = a0 + g_fcB[0];
        out[(size_t)gwarp * 2 + 1] = a1 + g_fcB[1];
    }
}

// ---------------------------------------------------------------------------
extern "C" void kernel_launch(void* const* d_in, const int* in_sizes, int n_in,
                              void* d_out, int out_size) {
    const float* inputs  = (const float*)d_in[0];
    const float* rel_rec = (const float*)d_in[1];
    const float* rel_snd = (const float*)d_in[2];
    const float* m1W1 = (const float*)d_in[3];  const float* m1b1 = (const float*)d_in[4];
    const float* m1W2 = (const float*)d_in[5];  const float* m1b2 = (const float*)d_in[6];
    const float* m2W1 = (const float*)d_in[7];  const float* m2b1 = (const float*)d_in[8];
    const float* m2W2 = (const float*)d_in[9];  const float* m2b2 = (const float*)d_in[10];
    const float* m3W1 = (const float*)d_in[11]; const float* m3b1 = (const float*)d_in[12];
    const float* m3W2 = (const float*)d_in[13]; const float* m3b2 = (const float*)d_in[14];
    const float* m4W1 = (const float*)d_in[15]; const float* m4b1 = (const float*)d_in[16];
    const float* m4W2 = (const float*)d_in[17]; const float* m4b2 = (const float*)d_in[18];
    const float* gmma = (const float*)d_in[19]; const float* beta = (const float*)d_in[20];
    const float* fcW  = (const float*)d_in[21]; const float* fcb  = (const float*)d_in[22];
    float* out = (float*)d_out;

    float *h1, *na, *nb, *as_, *ar_;
    __half *xskipH, *preH, *y4H, *wth, *wtl;
    cudaGetSymbolAddress((void**)&h1, g_h1);
    cudaGetSymbolAddress((void**)&na, g_na);
    cudaGetSymbolAddress((void**)&nb, g_nb);
    cudaGetSymbolAddress((void**)&as_, g_as);
    cudaGetSymbolAddress((void**)&ar_, g_ar);
    cudaGetSymbolAddress((void**)&xskipH, g_xskipH);
    cudaGetSymbolAddress((void**)&preH, g_preH);
    cudaGetSymbolAddress((void**)&y4H, g_y4H);
    cudaGetSymbolAddress((void**)&wth, g_WtHi);
    cudaGetSymbolAddress((void**)&wtl, g_WtLo);

    cudaFuncSetAttribute((const void*)gemm_tc<1,1,1>, cudaFuncAttributeMaxDynamicSharedMemorySize, DSMEM);
    cudaFuncSetAttribute((const void*)gemm_tc<3,1,1>, cudaFuncAttributeMaxDynamicSharedMemorySize, DSMEM);
    cudaFuncSetAttribute((const void*)gemm_tc<2,1,2>, cudaFuncAttributeMaxDynamicSharedMemorySize, DSMEM);

    dim3 gN(BNr / 64, 4);
    dim3 gN2(BNr / 64, 8);
    dim3 gE(NCTA, 2);
    dim3 tb(32, 32);
    dim3 tg(8, 8);

    // edge index tables + weight prep (transpose + fp16 split)
    build_idx_k<<<(Ee + 127) / 128, 128>>>(rel_rec, rel_snd);
    prep_wt_k<<<tg, tb>>>(m2W2,             wth + 0 * 65536, wtl + 0 * 65536);
    prep_wt_k<<<tg, tb>>>(m4W1 + 512 * 256, wth + 1 * 65536, wtl + 1 * 65536);
    prep_wt_k<<<tg, tb>>>(m4W2,             wth + 2 * 65536, wtl + 2 * 65536);

    // mlp1 (node level)
    gemm_node<<<gN, 256>>>(inputs, FIN, FIN, m1W1, m1b1, 1, na);
    gemm_node<<<gN, 256>>>(na, Hh, Hh, m1W2, m1b2, 1, h1);

    // node projections for mlp2 layer1 (send + recv halves, one launch)
    gemm_node2<<<gN2, 256>>>(h1, m2W1, m2W1 + 256*256, as_, ar_);

    // big GEMM #1 (single-term W): xskipH = fp16(ELU(ELU(as[s]+ar[r]+b1) @ W2 + b2))
    gemm_tc<1,1,1><<<gE, 256, DSMEM>>>(nullptr, wth + 0 * 65536, wtl + 0 * 65536,
                                       as_, ar_, m2b1, m2b2, 1, xskipH);

    // edge2node + mlp3 (node level)
    edge2node_k<<<BNr, 256>>>(xskipH, na);
    gemm_node<<<gN, 256>>>(na, Hh, Hh, m3W1, m3b1, 1, nb);
    gemm_node<<<gN, 256>>>(nb, Hh, Hh, m3W2, m3b2, 1, h1);

    // node projections for mlp4 layer1
    gemm_node2<<<gN2, 256>>>(h1, m4W1, m4W1 + 256*256, as_, ar_);

    // big GEMM #2 (single-term W, pure cp.async A): preH = fp16(xskipH @ W4_1[512:768])
    gemm_tc<3,1,1><<<gE, 256, DSMEM>>>(xskipH, wth + 1 * 65536, wtl + 1 * 65536,
                                       nullptr, nullptr, nullptr, nullptr, 0, preH);

    // big GEMM #3 (2-term W): y4H = fp16(ELU(ELU(preH + as[s]+ar[r]+b1) @ W4_2 + b2))
    //                          + fused per-CTA BN partial stats (fp32 pre-rounding)
    gemm_tc<2,1,2><<<gE, 256, DSMEM>>>(preH, wth + 2 * 65536, wtl + 2 * 65536,
                                       as_, ar_, m4b1, m4b2, 1, y4H);

    // BN reduce (parallel deterministic), finalize, final fc
    bn_reduce_k<<<256, 256>>>();
    bn_fin3<<<1, 256>>>(gmma, beta, fcW, fcb);
    fc_k<<<(BE * 32 + 255) / 256, 256>>>(y4H, out);
}

// round 10
// speedup vs baseline: 2.2870x; 1.3508x over previous
#include <cuda_runtime.h>
#include <cuda_fp16.h>
#include <math.h>
#include <cstdint>

#define Bsz 32
#define Nn  100
#define Ee  9900
#define Hh  256
#define FIN 200
#define BE  (Bsz*Ee)    // 316800
#define BNr (Bsz*Nn)    // 3200
#define NCTA (BE/128)   // 2475

// ---------------- scratch (static device globals) ---------------------------
__device__ float g_h1[BNr*Hh];
__device__ float g_na[BNr*Hh];
__device__ float g_nb[BNr*Hh];
__device__ float g_as[BNr*Hh];
__device__ float g_ar[BNr*Hh];
__device__ __half g_xskipH[(size_t)BE*Hh];
__device__ __half g_preH[(size_t)BE*Hh];
__device__ __half g_y4H[(size_t)BE*Hh];
__device__ int   g_send[Ee];
__device__ int   g_recv[Ee];
__device__ float g_p3[(size_t)NCTA*256*2];   // per-CTA BN partials (sum, sumsq)
__device__ double g_chS[256], g_chQ[256];
__device__ float g_fcW[Hh*2];
__device__ float g_fcB[2];
// transposed fp16-split weight images: [n][k] layout, 3 mats
__device__ __half g_WtHi[3][65536];
__device__ __half g_WtLo[3][65536];

__device__ __forceinline__ float elu_f(float x) { return x > 0.f ? x : expm1f(x); }
__device__ __forceinline__ float elu_fast(float x) {
    float e = __expf(fminf(x, 0.f)) - 1.f;
    return x > 0.f ? x : e;
}

__device__ __forceinline__ uint32_t smem_u32(const void* p) {
    uint32_t a;
    asm("{ .reg .u64 t; cvta.to.shared.u64 t, %1; cvt.u32.u64 %0, t; }" : "=r"(a) : "l"(p));
    return a;
}
__device__ __forceinline__ uint32_t pack_h2(__half a, __half b) {
    __half2 h2 = __halves2half2(a, b);
    return *reinterpret_cast<uint32_t*>(&h2);
}

#define LDSM4(r, addr) \
    asm volatile("ldmatrix.sync.aligned.m8n8.x4.shared.b16 {%0,%1,%2,%3}, [%4];" \
        : "=r"((r)[0]), "=r"((r)[1]), "=r"((r)[2]), "=r"((r)[3]) : "r"(addr))

#define MMA16816(d, a, b0, b1) \
    asm volatile("mma.sync.aligned.m16n8k16.row.col.f32.f16.f16.f32 " \
        "{%0,%1,%2,%3},{%4,%5,%6,%7},{%8,%9},{%0,%1,%2,%3};" \
        : "+f"((d)[0]), "+f"((d)[1]), "+f"((d)[2]), "+f"((d)[3]) \
        : "r"((a)[0]), "r"((a)[1]), "r"((a)[2]), "r"((a)[3]), "r"(b0), "r"(b1))

#define CP16(dst, src) \
    asm volatile("cp.async.ca.shared.global [%0], [%1], 16;" :: "r"(dst), "l"(src))
#define CP_COMMIT() asm volatile("cp.async.commit_group;" ::: "memory")
#define CP_WAIT0()  asm volatile("cp.async.wait_group 0;" ::: "memory")

// ---------------- edge index extraction -------------------------------------
__global__ void build_idx_k(const float* __restrict__ rr, const float* __restrict__ rs) {
    int e = blockIdx.x * blockDim.x + threadIdx.x;
    if (e >= Ee) return;
    int r = 0, s = 0;
    for (int n = 0; n < Nn; n++) {
        if (rr[e*Nn + n] > 0.5f) r = n;
        if (rs[e*Nn + n] > 0.5f) s = n;
    }
    g_recv[e] = r;
    g_send[e] = s;
}

// ---------------- weight prep: transpose [k][n]->[n][k] + fp16 split --------
__global__ void prep_wt_k(const float* __restrict__ W,
                          __half* __restrict__ Hi, __half* __restrict__ Lo) {
    __shared__ float t[32][33];
    int k0 = blockIdx.x * 32, n0 = blockIdx.y * 32;
    int tx = threadIdx.x, ty = threadIdx.y;
    t[ty][tx] = W[(k0 + ty) * 256 + n0 + tx];
    __syncthreads();
    float v = t[tx][ty];
    __half h = __float2half_rn(v);
    __half l = __float2half_rn(v - __half2float(h));
    Hi[(n0 + ty) * 256 + k0 + tx] = h;
    Lo[(n0 + ty) * 256 + k0 + tx] = l;
}

// ---------------- big tensor-core GEMM: M128 x N256, 512 threads ------------
// K=256 in 4 chunks of 64, double-buffered, 1 CTA/SM.
// AMODE 1: A = ELU(As[s]+Ar[r]+b1)            fp32 sources
// AMODE 2: A = ELU(preH + As[s]+Ar[r]+b1)     preH fp16
// AMODE 3: A = AmatH (fp16, direct cp.async)
// OUTF16:  store C as fp16; WTERMS: 1 = hi-only W, 2 = hi+lo split
#define ASTR  144
#define ABYTES 18432
#define BHIOF  18432
#define BLOOF  55296

template<int AMODE, int OUTF16, int WTERMS>
__global__ __launch_bounds__(512, 1)
void gemm_tc(const __half* __restrict__ AmatH,
             const __half* __restrict__ WtHi, const __half* __restrict__ WtLo,
             const float* __restrict__ As_, const float* __restrict__ Ar_,
             const float* __restrict__ b1,
             const float* __restrict__ bias, int do_elu,
             void* __restrict__ Cout)
{
    constexpr int BUFSZ = (WTERMS == 2) ? 92160 : 55296;
    extern __shared__ char sm[];
    __shared__ int sidx[128], ridx[128];

    const int tid  = threadIdx.x;
    const int lane = tid & 31, w = tid >> 5;
    const int row0 = blockIdx.x * 128;
    const uint32_t sbase = smem_u32(sm);

    const int rowA = tid >> 2;            // 128 rows, 4 threads/row
    const int q0   = (tid & 3) * 16;      // 16 k-elements per thread
    const size_t arow = (size_t)(row0 + rowA) * 256;

    // B async copy for chunk cc into buffer bf (hi [+ lo], 256 rows x 128B)
    #define CPB(cc, bf) do { \
        _Pragma("unroll") \
        for (int i = 0; i < WTERMS * 4; ++i) { \
            int seg = tid + i * 512; \
            int isLo = seg >> 11; \
            int rr = (seg >> 3) & 255; \
            int q  = seg & 7; \
            const __half* src = (isLo ? WtLo : WtHi) + (size_t)rr * 256 + (cc) * 64 + q * 8; \
            uint32_t dst = sbase + (bf) * BUFSZ + (isLo ? BLOOF : BHIOF) + rr * ASTR + q * 16; \
            CP16(dst, (const char*)src); \
        } \
    } while (0)

    // A async copy (AMODE 3): fp16 source, straight to smem
    #define CPA3(cc, bf) do { \
        _Pragma("unroll") \
        for (int i = 0; i < 2; ++i) { \
            int seg = tid + i * 512; \
            int rr = seg >> 3; \
            int q  = seg & 7; \
            const __half* src = AmatH + (size_t)(row0 + rr) * 256 + (cc) * 64 + q * 8; \
            uint32_t dst = sbase + (bf) * BUFSZ + rr * ASTR + q * 16; \
            CP16(dst, (const char*)src); \
        } \
    } while (0)

    // A build (AMODE 1/2): gather + combine + ELU + fp16 + STS (16 el/thread)
    #define STSA(cc, bf) do { \
        char* adst = sm + (bf) * BUFSZ + rowA * ASTR + q0 * 2; \
        _Pragma("unroll") \
        for (int it = 0; it < 2; ++it) { \
            int k0 = (cc) * 64 + q0 + it * 8; \
            float4 s0 = *(const float4*)(As_ + si + k0); \
            float4 s1 = *(const float4*)(As_ + si + k0 + 4); \
            float4 r0 = *(const float4*)(Ar_ + ri + k0); \
            float4 r1 = *(const float4*)(Ar_ + ri + k0 + 4); \
            float4 c0 = *(const float4*)(b1 + k0); \
            float4 c1 = *(const float4*)(b1 + k0 + 4); \
            float v0=s0.x+r0.x+c0.x, v1=s0.y+r0.y+c0.y, v2=s0.z+r0.z+c0.z, v3=s0.w+r0.w+c0.w; \
            float v4=s1.x+r1.x+c1.x, v5=s1.y+r1.y+c1.y, v6=s1.z+r1.z+c1.z, v7=s1.w+r1.w+c1.w; \
            if (AMODE == 2) { \
                uint4 pv = *(const uint4*)(AmatH + arow + k0); \
                float2 p0 = __half22float2(*(__half2*)&pv.x); \
                float2 p1 = __half22float2(*(__half2*)&pv.y); \
                float2 p2 = __half22float2(*(__half2*)&pv.z); \
                float2 p3 = __half22float2(*(__half2*)&pv.w); \
                v0+=p0.x; v1+=p0.y; v2+=p1.x; v3+=p1.y; \
                v4+=p2.x; v5+=p2.y; v6+=p3.x; v7+=p3.y; \
            } \
            v0=elu_fast(v0); v1=elu_fast(v1); v2=elu_fast(v2); v3=elu_fast(v3); \
            v4=elu_fast(v4); v5=elu_fast(v5); v6=elu_fast(v6); v7=elu_fast(v7); \
            uint4 o; \
            o.x = pack_h2(__float2half_rn(v0), __float2half_rn(v1)); \
            o.y = pack_h2(__float2half_rn(v2), __float2half_rn(v3)); \
            o.z = pack_h2(__float2half_rn(v4), __float2half_rn(v5)); \
            o.w = pack_h2(__float2half_rn(v6), __float2half_rn(v7)); \
            *(uint4*)(adst + it * 16) = o; \
        } \
    } while (0)

    // ---- prologue
    CPB(0, 0);
    if (AMODE == 3) CPA3(0, 0);
    CP_COMMIT();

    int si = 0, ri = 0;
    if (AMODE != 3) {
        if (tid < 128) {
            int row = row0 + tid;
            int b = row / Ee, e = row - b * Ee;
            sidx[tid] = (b * Nn + g_send[e]) * Hh;
            ridx[tid] = (b * Nn + g_recv[e]) * Hh;
        }
        __syncthreads();
        si = sidx[rowA]; ri = ridx[rowA];
        STSA(0, 0);
    }

    // ---- per-warp tile origin + ldmatrix lane addresses (16 warps: 4M x 4N)
    const int m0w = (w & 3) * 32;
    const int n0w = (w >> 2) * 64;
    const int laneA_row = (lane & 7) + ((lane >> 3) & 1) * 8;
    const int laneA_k   = ((lane >> 4) & 1) * 8;
    const int laneB_row = (lane & 7) + ((lane >> 4) & 1) * 8;
    const int laneB_k   = ((lane >> 3) & 1) * 8;

    uint32_t aOff[2], bOff[4];
    #pragma unroll
    for (int i = 0; i < 2; i++)
        aOff[i] = (uint32_t)((m0w + i*16 + laneA_row) * ASTR + laneA_k * 2);
    #pragma unroll
    for (int jp = 0; jp < 4; jp++)
        bOff[jp] = (uint32_t)(BHIOF + (n0w + jp*16 + laneB_row) * ASTR + laneB_k * 2);

    float acc[16][4];
    #pragma unroll
    for (int t = 0; t < 16; t++) { acc[t][0]=0.f; acc[t][1]=0.f; acc[t][2]=0.f; acc[t][3]=0.f; }

    // ---- mainloop: 4 chunks of K64
    #pragma unroll 1
    for (int c = 0; c < 4; ++c) {
        const int cur = c & 1, nxt = cur ^ 1;
        CP_WAIT0();
        __syncthreads();
        if (c < 3) {
            CPB(c + 1, nxt);
            if (AMODE == 3) CPA3(c + 1, nxt);
            CP_COMMIT();
            if (AMODE != 3) STSA(c + 1, nxt);
        }
        const uint32_t base = sbase + cur * BUFSZ;
        #pragma unroll
        for (int ks = 0; ks < 4; ++ks) {
            uint32_t ah[2][4];
            #pragma unroll
            for (int i = 0; i < 2; i++)
                LDSM4(ah[i], base + aOff[i] + ks * 32);
            #pragma unroll
            for (int jp = 0; jp < 4; jp++) {
                uint32_t bh4[4];
                LDSM4(bh4, base + bOff[jp] + ks * 32);
                MMA16816(acc[0*8+2*jp],   ah[0], bh4[0], bh4[1]);
                MMA16816(acc[0*8+2*jp+1], ah[0], bh4[2], bh4[3]);
                MMA16816(acc[1*8+2*jp],   ah[1], bh4[0], bh4[1]);
                MMA16816(acc[1*8+2*jp+1], ah[1], bh4[2], bh4[3]);
                if (WTERMS == 2) {
                    uint32_t bl4[4];
                    LDSM4(bl4, base + bOff[jp] + (BLOOF - BHIOF) + ks * 32);
                    MMA16816(acc[0*8+2*jp],   ah[0], bl4[0], bl4[1]);
                    MMA16816(acc[0*8+2*jp+1], ah[0], bl4[2], bl4[3]);
                    MMA16816(acc[1*8+2*jp],   ah[1], bl4[0], bl4[1]);
                    MMA16816(acc[1*8+2*jp+1], ah[1], bl4[2], bl4[3]);
                }
            }
        }
    }

    // ---- epilogue
    const int g  = lane >> 2;
    const int tg = lane & 3;
    float cs[16], cq[16];
    if (AMODE == 2) {
        #pragma unroll
        for (int t = 0; t < 16; ++t) { cs[t] = 0.f; cq[t] = 0.f; }
    }
    float* Cf = (float*)Cout;
    __half* Ch = (__half*)Cout;
    #pragma unroll
    for (int i = 0; i < 2; i++) {
        #pragma unroll
        for (int j = 0; j < 8; j++) {
            int colg = n0w + j*8 + tg*2;
            float b0v = 0.f, b1v = 0.f;
            if (bias) { b0v = __ldg(bias + colg); b1v = __ldg(bias + colg + 1); }
            float* q = acc[i*8+j];
            int rlo = row0 + m0w + i*16 + g;
            int rhi = rlo + 8;
            float2 o0, o1;
            o0.x = q[0] + b0v; o0.y = q[1] + b1v;
            o1.x = q[2] + b0v; o1.y = q[3] + b1v;
            if (do_elu) {
                o0.x = elu_fast(o0.x); o0.y = elu_fast(o0.y);
                o1.x = elu_fast(o1.x); o1.y = elu_fast(o1.y);
            }
            if (AMODE == 2) {
                cs[j*2+0] += o0.x + o1.x;
                cs[j*2+1] += o0.y + o1.y;
                cq[j*2+0] += o0.x*o0.x + o1.x*o1.x;
                cq[j*2+1] += o0.y*o0.y + o1.y*o1.y;
            }
            if (OUTF16) {
                *(uint32_t*)(Ch + (size_t)rlo * 256 + colg) =
                    pack_h2(__float2half_rn(o0.x), __float2half_rn(o0.y));
                *(uint32_t*)(Ch + (size_t)rhi * 256 + colg) =
                    pack_h2(__float2half_rn(o1.x), __float2half_rn(o1.y));
            } else {
                *(float2*)(Cf + (size_t)rlo * 256 + colg) = o0;
                *(float2*)(Cf + (size_t)rhi * 256 + colg) = o1;
            }
        }
    }

    if (AMODE == 2) {
        #pragma unroll
        for (int t = 0; t < 16; ++t) {
            #pragma unroll
            for (int o = 4; o <= 16; o <<= 1) {
                cs[t] += __shfl_xor_sync(0xffffffffu, cs[t], o);
                cq[t] += __shfl_xor_sync(0xffffffffu, cq[t], o);
            }
        }
        __syncthreads();
        float* sps = (float*)sm;          // [16 warps][64 local cols][2]
        if (lane < 4) {
            #pragma unroll
            for (int j = 0; j < 8; ++j) {
                #pragma unroll
                for (int par = 0; par < 2; ++par) {
                    int coll = j*8 + lane*2 + par;
                    sps[w*128 + coll*2 + 0] = cs[j*2+par];
                    sps[w*128 + coll*2 + 1] = cq[j*2+par];
                }
            }
        }
        __syncthreads();
        // 512 threads: one (col, stat) item each; sum the 4 M-warps per col
        int col = tid >> 1, stat = tid & 1;
        int nw4 = (col >> 6) * 4;
        float a2 = 0.f;
        #pragma unroll
        for (int mw = 0; mw < 4; ++mw)
            a2 += sps[(nw4 + mw)*128 + (col & 63)*2 + stat];
        g_p3[((size_t)blockIdx.x * 256 + col)*2 + stat] = a2;
    }
    #undef CPB
    #undef CPA3
    #undef STSA
}

// ---------------- small node-level SIMT GEMM (M=3200) -----------------------
__global__ __launch_bounds__(256)
void gemm_node(const float* __restrict__ A, int lda, int K,
               const float* __restrict__ W, const float* __restrict__ bias,
               int do_elu, float* __restrict__ C)
{
    __shared__ float sA[16][65];
    __shared__ float sB[16][64];
    const int row0 = blockIdx.x * 64;
    const int col0 = blockIdx.y * 64;
    const int tid  = threadIdx.x;
    const int ty   = tid >> 4, tx = tid & 15;
    float acc[4][4] = {};
    for (int kt = 0; kt < K; kt += 16) {
        #pragma unroll
        for (int i = 0; i < 4; i++) {
            int idx = tid + i * 256;
            int m = idx >> 4, k = idx & 15;
            int kk = kt + k;
            sA[k][m] = (kk < K) ? A[(size_t)(row0 + m) * lda + kk] : 0.f;
        }
        #pragma unroll
        for (int i = 0; i < 4; i++) {
            int idx = tid + i * 256;
            int k = idx >> 6, n = idx & 63;
            int kk = kt + k;
            sB[k][n] = (kk < K) ? W[(size_t)kk * 256 + col0 + n] : 0.f;
        }
        __syncthreads();
        #pragma unroll
        for (int k = 0; k < 16; k++) {
            float a[4], b[4];
            #pragma unroll
            for (int i = 0; i < 4; i++) a[i] = sA[k][ty*4 + i];
            #pragma unroll
            for (int j = 0; j < 4; j++) b[j] = sB[k][tx*4 + j];
            #pragma unroll
            for (int i = 0; i < 4; i++)
                #pragma unroll
                for (int j = 0; j < 4; j++)
                    acc[i][j] += a[i] * b[j];
        }
        __syncthreads();
    }
    #pragma unroll
    for (int i = 0; i < 4; i++) {
        int m = row0 + ty*4 + i;
        #pragma unroll
        for (int j = 0; j < 4; j++) {
            int n = col0 + tx*4 + j;
            float v = acc[i][j];
            if (bias) v += bias[n];
            if (do_elu) v = elu_f(v);
            C[(size_t)m * 256 + n] = v;
        }
    }
}

// ---------------- merged dual node GEMM: same A, two weight mats ------------
__global__ __launch_bounds__(256)
void gemm_node2(const float* __restrict__ A,
                const float* __restrict__ Wa, const float* __restrict__ Wb,
                float* __restrict__ Ca, float* __restrict__ Cb)
{
    const float* W = (blockIdx.y < 4) ? Wa : Wb;
    float* C       = (blockIdx.y < 4) ? Ca : Cb;
    const int col0 = (blockIdx.y & 3) * 64;
    __shared__ float sA[16][65];
    __shared__ float sB[16][64];
    const int row0 = blockIdx.x * 64;
    const int tid  = threadIdx.x;
    const int ty   = tid >> 4, tx = tid & 15;
    float acc[4][4] = {};
    for (int kt = 0; kt < 256; kt += 16) {
        #pragma unroll
        for (int i = 0; i < 4; i++) {
            int idx = tid + i * 256;
            int m = idx >> 4, k = idx & 15;
            sA[k][m] = A[(size_t)(row0 + m) * 256 + kt + k];
        }
        #pragma unroll
        for (int i = 0; i < 4; i++) {
            int idx = tid + i * 256;
            int k = idx >> 6, n = idx & 63;
            sB[k][n] = W[(size_t)(kt + k) * 256 + col0 + n];
        }
        __syncthreads();
        #pragma unroll
        for (int k = 0; k < 16; k++) {
            float a[4], b[4];
            #pragma unroll
            for (int i = 0; i < 4; i++) a[i] = sA[k][ty*4 + i];
            #pragma unroll
            for (int j = 0; j < 4; j++) b[j] = sB[k][tx*4 + j];
            #pragma unroll
            for (int i = 0; i < 4; i++)
                #pragma unroll
                for (int j = 0; j < 4; j++)
                    acc[i][j] += a[i] * b[j];
        }
        __syncthreads();
    }
    #pragma unroll
    for (int i = 0; i < 4; i++) {
        int m = row0 + ty*4 + i;
        #pragma unroll
        for (int j = 0; j < 4; j++)
            C[(size_t)m * 256 + col0 + tx*4 + j] = acc[i][j];
    }
}

// ---------------- edge2node: contiguous 99-edge segment mean (fp16 in) ------
__global__ void edge2node_k(const __half* __restrict__ x, float* __restrict__ out) {
    int nodeRow = blockIdx.x;
    int h = threadIdx.x;
    int b = nodeRow / Nn, n = nodeRow - b * Nn;
    const __half* base = x + (size_t)(b * Ee + n * 99) * Hh + h;
    float s = 0.f;
    #pragma unroll 3
    for (int r = 0; r < 99; r++) s += __half2float(base[(size_t)r * Hh]);
    out[(size_t)nodeRow * Hh + h] = s * (1.0f / 9900.0f);
}

// ---------------- BN partial reduce: parallel deterministic tree ------------
__global__ void bn_reduce_k() {
    int ch = blockIdx.x, t = threadIdx.x;
    double s = 0.0, q = 0.0;
    for (int bx = t; bx < NCTA; bx += 256) {
        s += (double)g_p3[((size_t)bx * 256 + ch) * 2 + 0];
        q += (double)g_p3[((size_t)bx * 256 + ch) * 2 + 1];
    }
    __shared__ double ss[256], sq[256];
    ss[t] = s; sq[t] = q;
    __syncthreads();
    for (int st = 128; st > 0; st >>= 1) {
        if (t < st) { ss[t] += ss[t + st]; sq[t] += sq[t + st]; }
        __syncthreads();
    }
    if (t == 0) { g_chS[ch] = ss[0]; g_chQ[ch] = sq[0]; }
}

// ---------------- BN finalize + fold into fc --------------------------------
__global__ void bn_fin3(const float* __restrict__ gamma, const float* __restrict__ beta,
                        const float* __restrict__ W, const float* __restrict__ fb) {
    int ch = threadIdx.x;
    double s = g_chS[ch], q = g_chQ[ch];
    double m = s / (double)BE;
    double v = q / (double)BE - m * m;
    float sc = (float)(rsqrt(v + 1e-5) * (double)gamma[ch]);
    float sh = beta[ch] - (float)m * sc;
    float w0 = W[ch*2 + 0], w1 = W[ch*2 + 1];
    g_fcW[ch*2 + 0] = sc * w0;
    g_fcW[ch*2 + 1] = sc * w1;
    __shared__ float r0s[256], r1s[256];
    r0s[ch] = sh * w0;
    r1s[ch] = sh * w1;
    __syncthreads();
    for (int st = 128; st > 0; st >>= 1) {
        if (ch < st) { r0s[ch] += r0s[ch + st]; r1s[ch] += r1s[ch + st]; }
        __syncthreads();
    }
    if (ch == 0) { g_fcB[0] = r0s[0] + fb[0]; g_fcB[1] = r1s[0] + fb[1]; }
}

// ---------------- final fc (folded BN): warp per row, fp16 y ----------------
__global__ void fc_k(const __half* __restrict__ y, float* __restrict__ out) {
    int gwarp = (blockIdx.x * blockDim.x + threadIdx.x) >> 5;
    int lane  = threadIdx.x & 31;
    if (gwarp >= BE) return;
    const __half2* row = (const __half2*)(y + (size_t)gwarp * Hh);
    float a0 = 0.f, a1 = 0.f;
    #pragma unroll
    for (int i = lane; i < 128; i += 32) {
        float2 v = __half22float2(row[i]);
        int ch = i * 2;
        a0 += v.x * g_fcW[ch*2 + 0] + v.y * g_fcW[ch*2 + 2];
        a1 += v.x * g_fcW[ch*2 + 1] + v.y * g_fcW[ch*2 + 3];
    }
    #pragma unroll
    for (int o = 16; o > 0; o >>= 1) {
        a0 += __shfl_down_sync(0xffffffffu, a0, o);
        a1 += __shfl_down_sync(0xffffffffu, a1, o);
    }
    if (lane == 0) {
        out[(size_t)gwarp * 2 + 0] = a0 + g_fcB[0];
        out[(size_t)gwarp * 2 + 1] = a1 + g_fcB[1];
    }
}

// ---------------------------------------------------------------------------
extern "C" void kernel_launch(void* const* d_in, const int* in_sizes, int n_in,
                              void* d_out, int out_size) {
    const float* inputs  = (const float*)d_in[0];
    const float* rel_rec = (const float*)d_in[1];
    const float* rel_snd = (const float*)d_in[2];
    const float* m1W1 = (const float*)d_in[3];  const float* m1b1 = (const float*)d_in[4];
    const float* m1W2 = (const float*)d_in[5];  const float* m1b2 = (const float*)d_in[6];
    const float* m2W1 = (const float*)d_in[7];  const float* m2b1 = (const float*)d_in[8];
    const float* m2W2 = (const float*)d_in[9];  const float* m2b2 = (const float*)d_in[10];
    const float* m3W1 = (const float*)d_in[11]; const float* m3b1 = (const float*)d_in[12];
    const float* m3W2 = (const float*)d_in[13]; const float* m3b2 = (const float*)d_in[14];
    const float* m4W1 = (const float*)d_in[15]; const float* m4b1 = (const float*)d_in[16];
    const float* m4W2 = (const float*)d_in[17]; const float* m4b2 = (const float*)d_in[18];
    const float* gmma = (const float*)d_in[19]; const float* beta = (const float*)d_in[20];
    const float* fcW  = (const float*)d_in[21]; const float* fcb  = (const float*)d_in[22];
    float* out = (float*)d_out;

    float *h1, *na, *nb, *as_, *ar_;
    __half *xskipH, *preH, *y4H, *wth, *wtl;
    cudaGetSymbolAddress((void**)&h1, g_h1);
    cudaGetSymbolAddress((void**)&na, g_na);
    cudaGetSymbolAddress((void**)&nb, g_nb);
    cudaGetSymbolAddress((void**)&as_, g_as);
    cudaGetSymbolAddress((void**)&ar_, g_ar);
    cudaGetSymbolAddress((void**)&xskipH, g_xskipH);
    cudaGetSymbolAddress((void**)&preH, g_preH);
    cudaGetSymbolAddress((void**)&y4H, g_y4H);
    cudaGetSymbolAddress((void**)&wth, g_WtHi);
    cudaGetSymbolAddress((void**)&wtl, g_WtLo);

    const int DS1 = 2 * 55296;   // 1-term: 110592
    const int DS2 = 2 * 92160;   // 2-term: 184320
    cudaFuncSetAttribute((const void*)gemm_tc<1,1,1>, cudaFuncAttributeMaxDynamicSharedMemorySize, DS1);
    cudaFuncSetAttribute((const void*)gemm_tc<3,1,1>, cudaFuncAttributeMaxDynamicSharedMemorySize, DS1);
    cudaFuncSetAttribute((const void*)gemm_tc<2,1,2>, cudaFuncAttributeMaxDynamicSharedMemorySize, DS2);

    dim3 gN(BNr / 64, 4);
    dim3 gN2(BNr / 64, 8);
    dim3 tb(32, 32);
    dim3 tg(8, 8);

    // edge index tables + weight prep (transpose + fp16 split)
    build_idx_k<<<(Ee + 127) / 128, 128>>>(rel_rec, rel_snd);
    prep_wt_k<<<tg, tb>>>(m2W2,             wth + 0 * 65536, wtl + 0 * 65536);
    prep_wt_k<<<tg, tb>>>(m4W1 + 512 * 256, wth + 1 * 65536, wtl + 1 * 65536);
    prep_wt_k<<<tg, tb>>>(m4W2,             wth + 2 * 65536, wtl + 2 * 65536);

    // mlp1 (node level)
    gemm_node<<<gN, 256>>>(inputs, FIN, FIN, m1W1, m1b1, 1, na);
    gemm_node<<<gN, 256>>>(na, Hh, Hh, m1W2, m1b2, 1, h1);

    // node projections for mlp2 layer1 (send + recv halves, one launch)
    gemm_node2<<<gN2, 256>>>(h1, m2W1, m2W1 + 256*256, as_, ar_);

    // big GEMM #1 (1-term W, wide-N): xskipH = fp16(ELU(ELU(as[s]+ar[r]+b1) @ W2 + b2))
    gemm_tc<1,1,1><<<NCTA, 512, DS1>>>(nullptr, wth + 0 * 65536, wtl + 0 * 65536,
                                       as_, ar_, m2b1, m2b2, 1, xskipH);

    // edge2node + mlp3 (node level)
    edge2node_k<<<BNr, 256>>>(xskipH, na);
    gemm_node<<<gN, 256>>>(na, Hh, Hh, m3W1, m3b1, 1, nb);
    gemm_node<<<gN, 256>>>(nb, Hh, Hh, m3W2, m3b2, 1, h1);

    // node projections for mlp4 layer1
    gemm_node2<<<gN2, 256>>>(h1, m4W1, m4W1 + 256*256, as_, ar_);

    // big GEMM #2 (1-term W, pure cp.async A): preH = fp16(xskipH @ W4_1[512:768])
    gemm_tc<3,1,1><<<NCTA, 512, DS1>>>(xskipH, wth + 1 * 65536, wtl + 1 * 65536,
                                       nullptr, nullptr, nullptr, nullptr, 0, preH);

    // big GEMM #3 (2-term W): y4H = fp16(ELU(ELU(preH + as[s]+ar[r]+b1) @ W4_2 + b2))
    //                          + fused per-CTA BN partial stats (fp32 pre-rounding)
    gemm_tc<2,1,2><<<NCTA, 512, DS2>>>(preH, wth + 2 * 65536, wtl + 2 * 65536,
                                       as_, ar_, m4b1, m4b2, 1, y4H);

    // BN reduce (parallel deterministic), finalize, final fc
    bn_reduce_k<<<256, 256>>>();
    bn_fin3<<<1, 256>>>(gmma, beta, fcW, fcb);
    fc_k<<<(BE * 32 + 255) / 256, 256>>>(y4H, out);
}

// round 11
// speedup vs baseline: 2.4063x; 1.0522x over previous
#include <cuda_runtime.h>
#include <cuda_fp16.h>
#include <math.h>
#include <cstdint>

#define Bsz 32
#define Nn  100
#define Ee  9900
#define Hh  256
#define FIN 200
#define BE  (Bsz*Ee)    // 316800
#define BNr (Bsz*Nn)    // 3200
#define NCTA (BE/128)   // 2475

// ---------------- scratch (static device globals) ---------------------------
__device__ float g_h1[BNr*Hh];
__device__ float g_na[BNr*Hh];
__device__ float g_nb[BNr*Hh];
__device__ float g_as[BNr*Hh];
__device__ float g_ar[BNr*Hh];
__device__ __half g_xskipH[(size_t)BE*Hh];
__device__ __half g_y4H[(size_t)BE*Hh];
__device__ int   g_send[Ee];
__device__ int   g_recv[Ee];
__device__ float g_p3[(size_t)NCTA*256*2];   // per-CTA BN partials (sum, sumsq)
__device__ double g_chS[256], g_chQ[256];
__device__ float g_fcW[Hh*2];
__device__ float g_fcB[2];
// transposed fp16-split weight images: [n][k] layout, 3 mats
__device__ __half g_WtHi[3][65536];
__device__ __half g_WtLo[3][65536];

__device__ __forceinline__ float elu_f(float x) { return x > 0.f ? x : expm1f(x); }
__device__ __forceinline__ float elu_fast(float x) {
    float e = __expf(fminf(x, 0.f)) - 1.f;
    return x > 0.f ? x : e;
}

__device__ __forceinline__ uint32_t smem_u32(const void* p) {
    uint32_t a;
    asm("{ .reg .u64 t; cvta.to.shared.u64 t, %1; cvt.u32.u64 %0, t; }" : "=r"(a) : "l"(p));
    return a;
}
__device__ __forceinline__ uint32_t pack_h2(__half a, __half b) {
    __half2 h2 = __halves2half2(a, b);
    return *reinterpret_cast<uint32_t*>(&h2);
}

#define LDSM4(r, addr) \
    asm volatile("ldmatrix.sync.aligned.m8n8.x4.shared.b16 {%0,%1,%2,%3}, [%4];" \
        : "=r"((r)[0]), "=r"((r)[1]), "=r"((r)[2]), "=r"((r)[3]) : "r"(addr))

#define MMA16816(d, a, b0, b1) \
    asm volatile("mma.sync.aligned.m16n8k16.row.col.f32.f16.f16.f32 " \
        "{%0,%1,%2,%3},{%4,%5,%6,%7},{%8,%9},{%0,%1,%2,%3};" \
        : "+f"((d)[0]), "+f"((d)[1]), "+f"((d)[2]), "+f"((d)[3]) \
        : "r"((a)[0]), "r"((a)[1]), "r"((a)[2]), "r"((a)[3]), "r"(b0), "r"(b1))

#define CP16(dst, src) \
    asm volatile("cp.async.ca.shared.global [%0], [%1], 16;" :: "r"(dst), "l"(src))
#define CP_COMMIT() asm volatile("cp.async.commit_group;" ::: "memory")
#define CP_WAIT0()  asm volatile("cp.async.wait_group 0;" ::: "memory")

// ---------------- edge index extraction -------------------------------------
__global__ void build_idx_k(const float* __restrict__ rr, const float* __restrict__ rs) {
    int e = blockIdx.x * blockDim.x + threadIdx.x;
    if (e >= Ee) return;
    int r = 0, s = 0;
    for (int n = 0; n < Nn; n++) {
        if (rr[e*Nn + n] > 0.5f) r = n;
        if (rs[e*Nn + n] > 0.5f) s = n;
    }
    g_recv[e] = r;
    g_send[e] = s;
}

// ---------------- weight prep: transpose [k][n]->[n][k] + fp16 split --------
__global__ void prep_wt_k(const float* __restrict__ W,
                          __half* __restrict__ Hi, __half* __restrict__ Lo) {
    __shared__ float t[32][33];
    int k0 = blockIdx.x * 32, n0 = blockIdx.y * 32;
    int tx = threadIdx.x, ty = threadIdx.y;
    t[ty][tx] = W[(k0 + ty) * 256 + n0 + tx];
    __syncthreads();
    float v = t[tx][ty];
    __half h = __float2half_rn(v);
    __half l = __float2half_rn(v - __half2float(h));
    Hi[(n0 + ty) * 256 + k0 + tx] = h;
    Lo[(n0 + ty) * 256 + k0 + tx] = l;
}

// ---------------- GEMM1: M128 x N256, 512 threads, 1-term W -----------------
// A = ELU(As[s]+Ar[r]+b1), out fp16. K=256 in 4 chunks of 64, double-buffered.
#define ASTR  144
#define BHIOF  18432
#define G1BUF  55296
#define G1DS   (2*G1BUF)   // 110592

__global__ __launch_bounds__(512, 1)
void gemm_g1(const __half* __restrict__ WtHi,
             const float* __restrict__ As_, const float* __restrict__ Ar_,
             const float* __restrict__ b1,
             const float* __restrict__ bias,
             __half* __restrict__ Cout)
{
    extern __shared__ char sm[];
    __shared__ int sidx[128], ridx[128];

    const int tid  = threadIdx.x;
    const int lane = tid & 31, w = tid >> 5;
    const int row0 = blockIdx.x * 128;
    const uint32_t sbase = smem_u32(sm);

    const int rowA = tid >> 2;
    const int q0   = (tid & 3) * 16;

    #define CPB1(cc, bf) do { \
        _Pragma("unroll") \
        for (int i = 0; i < 4; ++i) { \
            int seg = tid + i * 512; \
            int rr = (seg >> 3) & 255; \
            int q  = seg & 7; \
            const __half* src = WtHi + (size_t)rr * 256 + (cc) * 64 + q * 8; \
            CP16(sbase + (bf) * G1BUF + BHIOF + rr * ASTR + q * 16, (const char*)src); \
        } \
    } while (0)

    #define STSA1(cc, bf) do { \
        char* adst = sm + (bf) * G1BUF + rowA * ASTR + q0 * 2; \
        _Pragma("unroll") \
        for (int it = 0; it < 2; ++it) { \
            int k0 = (cc) * 64 + q0 + it * 8; \
            float4 s0 = *(const float4*)(As_ + si + k0); \
            float4 s1 = *(const float4*)(As_ + si + k0 + 4); \
            float4 r0 = *(const float4*)(Ar_ + ri + k0); \
            float4 r1 = *(const float4*)(Ar_ + ri + k0 + 4); \
            float4 c0 = *(const float4*)(b1 + k0); \
            float4 c1 = *(const float4*)(b1 + k0 + 4); \
            float v0=elu_fast(s0.x+r0.x+c0.x), v1=elu_fast(s0.y+r0.y+c0.y); \
            float v2=elu_fast(s0.z+r0.z+c0.z), v3=elu_fast(s0.w+r0.w+c0.w); \
            float v4=elu_fast(s1.x+r1.x+c1.x), v5=elu_fast(s1.y+r1.y+c1.y); \
            float v6=elu_fast(s1.z+r1.z+c1.z), v7=elu_fast(s1.w+r1.w+c1.w); \
            uint4 o; \
            o.x = pack_h2(__float2half_rn(v0), __float2half_rn(v1)); \
            o.y = pack_h2(__float2half_rn(v2), __float2half_rn(v3)); \
            o.z = pack_h2(__float2half_rn(v4), __float2half_rn(v5)); \
            o.w = pack_h2(__float2half_rn(v6), __float2half_rn(v7)); \
            *(uint4*)(adst + it * 16) = o; \
        } \
    } while (0)

    CPB1(0, 0);
    CP_COMMIT();
    if (tid < 128) {
        int row = row0 + tid;
        int b = row / Ee, e = row - b * Ee;
        sidx[tid] = (b * Nn + g_send[e]) * Hh;
        ridx[tid] = (b * Nn + g_recv[e]) * Hh;
    }
    __syncthreads();
    const int si = sidx[rowA], ri = ridx[rowA];
    STSA1(0, 0);

    const int m0w = (w & 3) * 32;
    const int n0w = (w >> 2) * 64;
    const int laneA_row = (lane & 7) + ((lane >> 3) & 1) * 8;
    const int laneA_k   = ((lane >> 4) & 1) * 8;
    const int laneB_row = (lane & 7) + ((lane >> 4) & 1) * 8;
    const int laneB_k   = ((lane >> 3) & 1) * 8;

    uint32_t aOff[2], bOff[4];
    #pragma unroll
    for (int i = 0; i < 2; i++)
        aOff[i] = (uint32_t)((m0w + i*16 + laneA_row) * ASTR + laneA_k * 2);
    #pragma unroll
    for (int jp = 0; jp < 4; jp++)
        bOff[jp] = (uint32_t)(BHIOF + (n0w + jp*16 + laneB_row) * ASTR + laneB_k * 2);

    float acc[16][4];
    #pragma unroll
    for (int t = 0; t < 16; t++) { acc[t][0]=0.f; acc[t][1]=0.f; acc[t][2]=0.f; acc[t][3]=0.f; }

    #pragma unroll 1
    for (int c = 0; c < 4; ++c) {
        const int cur = c & 1, nxt = cur ^ 1;
        CP_WAIT0();
        __syncthreads();
        if (c < 3) {
            CPB1(c + 1, nxt);
            CP_COMMIT();
            STSA1(c + 1, nxt);
        }
        const uint32_t base = sbase + cur * G1BUF;
        #pragma unroll
        for (int ks = 0; ks < 4; ++ks) {
            uint32_t ah[2][4];
            #pragma unroll
            for (int i = 0; i < 2; i++)
                LDSM4(ah[i], base + aOff[i] + ks * 32);
            #pragma unroll
            for (int jp = 0; jp < 4; jp++) {
                uint32_t bh4[4];
                LDSM4(bh4, base + bOff[jp] + ks * 32);
                MMA16816(acc[0*8+2*jp],   ah[0], bh4[0], bh4[1]);
                MMA16816(acc[0*8+2*jp+1], ah[0], bh4[2], bh4[3]);
                MMA16816(acc[1*8+2*jp],   ah[1], bh4[0], bh4[1]);
                MMA16816(acc[1*8+2*jp+1], ah[1], bh4[2], bh4[3]);
            }
        }
    }

    const int g  = lane >> 2;
    const int tg = lane & 3;
    #pragma unroll
    for (int i = 0; i < 2; i++) {
        #pragma unroll
        for (int j = 0; j < 8; j++) {
            int colg = n0w + j*8 + tg*2;
            float b0v = __ldg(bias + colg), b1v = __ldg(bias + colg + 1);
            float* q = acc[i*8+j];
            int rlo = row0 + m0w + i*16 + g;
            int rhi = rlo + 8;
            float o0 = elu_fast(q[0] + b0v), o1 = elu_fast(q[1] + b1v);
            float o2 = elu_fast(q[2] + b0v), o3 = elu_fast(q[3] + b1v);
            *(uint32_t*)(Cout + (size_t)rlo * 256 + colg) = pack_h2(__float2half_rn(o0), __float2half_rn(o1));
            *(uint32_t*)(Cout + (size_t)rhi * 256 + colg) = pack_h2(__float2half_rn(o2), __float2half_rn(o3));
        }
    }
    #undef CPB1
    #undef STSA1
}

// ---------------- fused GEMM2+GEMM3 -----------------------------------------
// stage 1: pre = xskipH @ W1 (1-term, fp32 acc, NO fp16 rounding of pre)
// A2 = fp16(ELU(pre + As[s]+Ar[r]+b1)) resident in smem (stride 528)
// stage 2: y4 = fp16(ELU(A2 @ (W2hi + W2lo) + b2)) + BN partials
#define F_STG   67584                 // staging region base (A2 = [0, 67584))
#define F_S1BUF 55296                 // stage-1: A1 18432 + B1hi 36864
#define F_S2BUF 73728                 // stage-2: Bhi 36864 + Blo 36864
#define F_DS    (F_STG + 2*F_S2BUF)   // 215040

__global__ __launch_bounds__(512, 1)
void gemm_f23(const __half* __restrict__ AmatH,
              const __half* __restrict__ W1Hi,
              const __half* __restrict__ W2Hi, const __half* __restrict__ W2Lo,
              const float* __restrict__ As_, const float* __restrict__ Ar_,
              const float* __restrict__ b1, const float* __restrict__ bias,
              __half* __restrict__ Cout)
{
    extern __shared__ char sm[];
    __shared__ int sidx[128], ridx[128];

    const int tid  = threadIdx.x;
    const int lane = tid & 31, w = tid >> 5;
    const int row0 = blockIdx.x * 128;
    const uint32_t sbase = smem_u32(sm);

    // stage-1 A copy: xskipH rows (fp16) straight into staging
    #define CPA1(cc, bf) do { \
        _Pragma("unroll") \
        for (int i = 0; i < 2; ++i) { \
            int seg = tid + i * 512; \
            int rr = seg >> 3, q = seg & 7; \
            const __half* src = AmatH + (size_t)(row0 + rr) * 256 + (cc) * 64 + q * 8; \
            CP16(sbase + F_STG + (bf) * F_S1BUF + rr * ASTR + q * 16, (const char*)src); \
        } \
    } while (0)
    #define CPB1f(cc, bf) do { \
        _Pragma("unroll") \
        for (int i = 0; i < 4; ++i) { \
            int seg = tid + i * 512; \
            int rr = (seg >> 3) & 255, q = seg & 7; \
            const __half* src = W1Hi + (size_t)rr * 256 + (cc) * 64 + q * 8; \
            CP16(sbase + F_STG + (bf) * F_S1BUF + 18432 + rr * ASTR + q * 16, (const char*)src); \
        } \
    } while (0)
    #define CPB2(cc, bf) do { \
        _Pragma("unroll") \
        for (int i = 0; i < 8; ++i) { \
            int seg = tid + i * 512; \
            int isLo = seg >> 11; \
            int rr = (seg >> 3) & 255, q = seg & 7; \
            const __half* src = (isLo ? W2Lo : W2Hi) + (size_t)rr * 256 + (cc) * 64 + q * 8; \
            CP16(sbase + F_STG + (bf) * F_S2BUF + (isLo ? 36864 : 0) + rr * ASTR + q * 16, (const char*)src); \
        } \
    } while (0)

    // ---- prologue: stage-1 chunk 0
    CPA1(0, 0);
    CPB1f(0, 0);
    CP_COMMIT();
    if (tid < 128) {
        int row = row0 + tid;
        int b = row / Ee, e = row - b * Ee;
        sidx[tid] = (b * Nn + g_send[e]) * Hh;
        ridx[tid] = (b * Nn + g_recv[e]) * Hh;
    }

    const int m0w = (w & 3) * 32;
    const int n0w = (w >> 2) * 64;
    const int laneA_row = (lane & 7) + ((lane >> 3) & 1) * 8;
    const int laneA_k   = ((lane >> 4) & 1) * 8;
    const int laneB_row = (lane & 7) + ((lane >> 4) & 1) * 8;
    const int laneB_k   = ((lane >> 3) & 1) * 8;

    uint32_t aOff1[2], bOff1[4];
    #pragma unroll
    for (int i = 0; i < 2; i++)
        aOff1[i] = (uint32_t)((m0w + i*16 + laneA_row) * ASTR + laneA_k * 2);
    #pragma unroll
    for (int jp = 0; jp < 4; jp++)
        bOff1[jp] = (uint32_t)(18432 + (n0w + jp*16 + laneB_row) * ASTR + laneB_k * 2);

    float acc[16][4];
    #pragma unroll
    for (int t = 0; t < 16; t++) { acc[t][0]=0.f; acc[t][1]=0.f; acc[t][2]=0.f; acc[t][3]=0.f; }

    // ---- stage-1 mainloop (1-term)
    #pragma unroll 1
    for (int c = 0; c < 4; ++c) {
        const int cur = c & 1, nxt = cur ^ 1;
        CP_WAIT0();
        __syncthreads();
        if (c < 3) {
            CPA1(c + 1, nxt);
            CPB1f(c + 1, nxt);
            CP_COMMIT();
        }
        const uint32_t base = sbase + F_STG + cur * F_S1BUF;
        #pragma unroll
        for (int ks = 0; ks < 4; ++ks) {
            uint32_t ah[2][4];
            #pragma unroll
            for (int i = 0; i < 2; i++)
                LDSM4(ah[i], base + aOff1[i] + ks * 32);
            #pragma unroll
            for (int jp = 0; jp < 4; jp++) {
                uint32_t bh4[4];
                LDSM4(bh4, base + bOff1[jp] + ks * 32);
                MMA16816(acc[0*8+2*jp],   ah[0], bh4[0], bh4[1]);
                MMA16816(acc[0*8+2*jp+1], ah[0], bh4[2], bh4[3]);
                MMA16816(acc[1*8+2*jp],   ah[1], bh4[0], bh4[1]);
                MMA16816(acc[1*8+2*jp+1], ah[1], bh4[2], bh4[3]);
            }
        }
    }
    __syncthreads();   // all stage-1 LDSM/MMA done -> staging region reusable

    // ---- stage-2 B chunk 0 in flight while A2 is built
    CPB2(0, 0);
    CP_COMMIT();

    // ---- build A2 = fp16(ELU(pre + As[s]+Ar[r]+b1)) into [0, 67584)
    const int g  = lane >> 2;
    const int tg = lane & 3;
    #pragma unroll
    for (int i = 0; i < 2; ++i) {
        int lr0 = m0w + i*16 + g;
        int lr1 = lr0 + 8;
        int s0i = sidx[lr0], r0i = ridx[lr0];
        int s1i = sidx[lr1], r1i = ridx[lr1];
        #pragma unroll
        for (int j = 0; j < 8; ++j) {
            int colg = n0w + j*8 + tg*2;
            float2 sa0 = *(const float2*)(As_ + s0i + colg);
            float2 ra0 = *(const float2*)(Ar_ + r0i + colg);
            float2 sa1 = *(const float2*)(As_ + s1i + colg);
            float2 ra1 = *(const float2*)(Ar_ + r1i + colg);
            float2 bb  = *(const float2*)(b1 + colg);
            float* q4 = acc[i*8+j];
            float v0 = elu_fast(q4[0] + sa0.x + ra0.x + bb.x);
            float v1 = elu_fast(q4[1] + sa0.y + ra0.y + bb.y);
            float v2 = elu_fast(q4[2] + sa1.x + ra1.x + bb.x);
            float v3 = elu_fast(q4[3] + sa1.y + ra1.y + bb.y);
            *(uint32_t*)(sm + lr0 * 528 + colg * 2) = pack_h2(__float2half_rn(v0), __float2half_rn(v1));
            *(uint32_t*)(sm + lr1 * 528 + colg * 2) = pack_h2(__float2half_rn(v2), __float2half_rn(v3));
        }
    }
    #pragma unroll
    for (int t = 0; t < 16; t++) { acc[t][0]=0.f; acc[t][1]=0.f; acc[t][2]=0.f; acc[t][3]=0.f; }

    uint32_t aOff2[2], bOff2[4];
    #pragma unroll
    for (int i = 0; i < 2; i++)
        aOff2[i] = (uint32_t)((m0w + i*16 + laneA_row) * 528 + laneA_k * 2);
    #pragma unroll
    for (int jp = 0; jp < 4; jp++)
        bOff2[jp] = (uint32_t)(F_STG + (n0w + jp*16 + laneB_row) * ASTR + laneB_k * 2);

    // ---- stage-2 mainloop (2-term, A2 resident)
    #pragma unroll 1
    for (int c = 0; c < 4; ++c) {
        const int cur = c & 1, nxt = cur ^ 1;
        CP_WAIT0();
        __syncthreads();    // first pass also publishes A2 stores
        if (c < 3) {
            CPB2(c + 1, nxt);
            CP_COMMIT();
        }
        const uint32_t koA = (uint32_t)(c * 128);
        const uint32_t bbase = sbase + cur * F_S2BUF;
        #pragma unroll
        for (int ks = 0; ks < 4; ++ks) {
            uint32_t ah[2][4];
            #pragma unroll
            for (int i = 0; i < 2; i++)
                LDSM4(ah[i], sbase + aOff2[i] + koA + ks * 32);
            #pragma unroll
            for (int jp = 0; jp < 4; jp++) {
                uint32_t bh4[4], bl4[4];
                LDSM4(bh4, bbase + bOff2[jp] + ks * 32);
                LDSM4(bl4, bbase + bOff2[jp] + 36864 + ks * 32);
                MMA16816(acc[0*8+2*jp],   ah[0], bh4[0], bh4[1]);
                MMA16816(acc[0*8+2*jp+1], ah[0], bh4[2], bh4[3]);
                MMA16816(acc[1*8+2*jp],   ah[1], bh4[0], bh4[1]);
                MMA16816(acc[1*8+2*jp+1], ah[1], bh4[2], bh4[3]);
                MMA16816(acc[0*8+2*jp],   ah[0], bl4[0], bl4[1]);
                MMA16816(acc[0*8+2*jp+1], ah[0], bl4[2], bl4[3]);
                MMA16816(acc[1*8+2*jp],   ah[1], bl4[0], bl4[1]);
                MMA16816(acc[1*8+2*jp+1], ah[1], bl4[2], bl4[3]);
            }
        }
    }

    // ---- epilogue: bias + ELU + fp16 stores + BN partials
    float cs[16], cq[16];
    #pragma unroll
    for (int t = 0; t < 16; ++t) { cs[t] = 0.f; cq[t] = 0.f; }
    #pragma unroll
    for (int i = 0; i < 2; i++) {
        #pragma unroll
        for (int j = 0; j < 8; j++) {
            int colg = n0w + j*8 + tg*2;
            float b0v = __ldg(bias + colg), b1v = __ldg(bias + colg + 1);
            float* q = acc[i*8+j];
            int rlo = row0 + m0w + i*16 + g;
            int rhi = rlo + 8;
            float o0 = elu_fast(q[0] + b0v), o1 = elu_fast(q[1] + b1v);
            float o2 = elu_fast(q[2] + b0v), o3 = elu_fast(q[3] + b1v);
            cs[j*2+0] += o0 + o2;
            cs[j*2+1] += o1 + o3;
            cq[j*2+0] += o0*o0 + o2*o2;
            cq[j*2+1] += o1*o1 + o3*o3;
            *(uint32_t*)(Cout + (size_t)rlo * 256 + colg) = pack_h2(__float2half_rn(o0), __float2half_rn(o1));
            *(uint32_t*)(Cout + (size_t)rhi * 256 + colg) = pack_h2(__float2half_rn(o2), __float2half_rn(o3));
        }
    }

    #pragma unroll
    for (int t = 0; t < 16; ++t) {
        #pragma unroll
        for (int o = 4; o <= 16; o <<= 1) {
            cs[t] += __shfl_xor_sync(0xffffffffu, cs[t], o);
            cq[t] += __shfl_xor_sync(0xffffffffu, cq[t], o);
        }
    }
    __syncthreads();
    float* sps = (float*)sm;          // [16 warps][64 local cols][2]
    if (lane < 4) {
        #pragma unroll
        for (int j = 0; j < 8; ++j) {
            #pragma unroll
            for (int par = 0; par < 2; ++par) {
                int coll = j*8 + lane*2 + par;
                sps[w*128 + coll*2 + 0] = cs[j*2+par];
                sps[w*128 + coll*2 + 1] = cq[j*2+par];
            }
        }
    }
    __syncthreads();
    int col = tid >> 1, stat = tid & 1;
    int nw4 = (col >> 6) * 4;
    float a2 = 0.f;
    #pragma unroll
    for (int mw = 0; mw < 4; ++mw)
        a2 += sps[(nw4 + mw)*128 + (col & 63)*2 + stat];
    g_p3[((size_t)blockIdx.x * 256 + col)*2 + stat] = a2;
    #undef CPA1
    #undef CPB1f
    #undef CPB2
}

// ---------------- small node-level SIMT GEMM (M=3200) -----------------------
__global__ __launch_bounds__(256)
void gemm_node(const float* __restrict__ A, int lda, int K,
               const float* __restrict__ W, const float* __restrict__ bias,
               int do_elu, float* __restrict__ C)
{
    __shared__ float sA[16][65];
    __shared__ float sB[16][64];
    const int row0 = blockIdx.x * 64;
    const int col0 = blockIdx.y * 64;
    const int tid  = threadIdx.x;
    const int ty   = tid >> 4, tx = tid & 15;
    float acc[4][4] = {};
    for (int kt = 0; kt < K; kt += 16) {
        #pragma unroll
        for (int i = 0; i < 4; i++) {
            int idx = tid + i * 256;
            int m = idx >> 4, k = idx & 15;
            int kk = kt + k;
            sA[k][m] = (kk < K) ? A[(size_t)(row0 + m) * lda + kk] : 0.f;
        }
        #pragma unroll
        for (int i = 0; i < 4; i++) {
            int idx = tid + i * 256;
            int k = idx >> 6, n = idx & 63;
            int kk = kt + k;
            sB[k][n] = (kk < K) ? W[(size_t)kk * 256 + col0 + n] : 0.f;
        }
        __syncthreads();
        #pragma unroll
        for (int k = 0; k < 16; k++) {
            float a[4], b[4];
            #pragma unroll
            for (int i = 0; i < 4; i++) a[i] = sA[k][ty*4 + i];
            #pragma unroll
            for (int j = 0; j < 4; j++) b[j] = sB[k][tx*4 + j];
            #pragma unroll
            for (int i = 0; i < 4; i++)
                #pragma unroll
                for (int j = 0; j < 4; j++)
                    acc[i][j] += a[i] * b[j];
        }
        __syncthreads();
    }
    #pragma unroll
    for (int i = 0; i < 4; i++) {
        int m = row0 + ty*4 + i;
        #pragma unroll
        for (int j = 0; j < 4; j++) {
            int n = col0 + tx*4 + j;
            float v = acc[i][j];
            if (bias) v += bias[n];
            if (do_elu) v = elu_f(v);
            C[(size_t)m * 256 + n] = v;
        }
    }
}

// ---------------- merged dual node GEMM: same A, two weight mats ------------
__global__ __launch_bounds__(256)
void gemm_node2(const float* __restrict__ A,
                const float* __restrict__ Wa, const float* __restrict__ Wb,
                float* __restrict__ Ca, float* __restrict__ Cb)
{
    const float* W = (blockIdx.y < 4) ? Wa : Wb;
    float* C       = (blockIdx.y < 4) ? Ca : Cb;
    const int col0 = (blockIdx.y & 3) * 64;
    __shared__ float sA[16][65];
    __shared__ float sB[16][64];
    const int row0 = blockIdx.x * 64;
    const int tid  = threadIdx.x;
    const int ty   = tid >> 4, tx = tid & 15;
    float acc[4][4] = {};
    for (int kt = 0; kt < 256; kt += 16) {
        #pragma unroll
        for (int i = 0; i < 4; i++) {
            int idx = tid + i * 256;
            int m = idx >> 4, k = idx & 15;
            sA[k][m] = A[(size_t)(row0 + m) * 256 + kt + k];
        }
        #pragma unroll
        for (int i = 0; i < 4; i++) {
            int idx = tid + i * 256;
            int k = idx >> 6, n = idx & 63;
            sB[k][n] = W[(size_t)(kt + k) * 256 + col0 + n];
        }
        __syncthreads();
        #pragma unroll
        for (int k = 0; k < 16; k++) {
            float a[4], b[4];
            #pragma unroll
            for (int i = 0; i < 4; i++) a[i] = sA[k][ty*4 + i];
            #pragma unroll
            for (int j = 0; j < 4; j++) b[j] = sB[k][tx*4 + j];
            #pragma unroll
            for (int i = 0; i < 4; i++)
                #pragma unroll
                for (int j = 0; j < 4; j++)
                    acc[i][j] += a[i] * b[j];
        }
        __syncthreads();
    }
    #pragma unroll
    for (int i = 0; i < 4; i++) {
        int m = row0 + ty*4 + i;
        #pragma unroll
        for (int j = 0; j < 4; j++)
            C[(size_t)m * 256 + col0 + tx*4 + j] = acc[i][j];
    }
}

// ---------------- edge2node: contiguous 99-edge segment mean (fp16 in) ------
__global__ void edge2node_k(const __half* __restrict__ x, float* __restrict__ out) {
    int nodeRow = blockIdx.x;
    int h = threadIdx.x;
    int b = nodeRow / Nn, n = nodeRow - b * Nn;
    const __half* base = x + (size_t)(b * Ee + n * 99) * Hh + h;
    float s = 0.f;
    #pragma unroll 3
    for (int r = 0; r < 99; r++) s += __half2float(base[(size_t)r * Hh]);
    out[(size_t)nodeRow * Hh + h] = s * (1.0f / 9900.0f);
}

// ---------------- BN partial reduce: parallel deterministic tree ------------
__global__ void bn_reduce_k() {
    int ch = blockIdx.x, t = threadIdx.x;
    double s = 0.0, q = 0.0;
    for (int bx = t; bx < NCTA; bx += 256) {
        s += (double)g_p3[((size_t)bx * 256 + ch) * 2 + 0];
        q += (double)g_p3[((size_t)bx * 256 + ch) * 2 + 1];
    }
    __shared__ double ss[256], sq[256];
    ss[t] = s; sq[t] = q;
    __syncthreads();
    for (int st = 128; st > 0; st >>= 1) {
        if (t < st) { ss[t] += ss[t + st]; sq[t] += sq[t + st]; }
        __syncthreads();
    }
    if (t == 0) { g_chS[ch] = ss[0]; g_chQ[ch] = sq[0]; }
}

// ---------------- BN finalize + fold into fc --------------------------------
__global__ void bn_fin3(const float* __restrict__ gamma, const float* __restrict__ beta,
                        const float* __restrict__ W, const float* __restrict__ fb) {
    int ch = threadIdx.x;
    double s = g_chS[ch], q = g_chQ[ch];
    double m = s / (double)BE;
    double v = q / (double)BE - m * m;
    float sc = (float)(rsqrt(v + 1e-5) * (double)gamma[ch]);
    float sh = beta[ch] - (float)m * sc;
    float w0 = W[ch*2 + 0], w1 = W[ch*2 + 1];
    g_fcW[ch*2 + 0] = sc * w0;
    g_fcW[ch*2 + 1] = sc * w1;
    __shared__ float r0s[256], r1s[256];
    r0s[ch] = sh * w0;
    r1s[ch] = sh * w1;
    __syncthreads();
    for (int st = 128; st > 0; st >>= 1) {
        if (ch < st) { r0s[ch] += r0s[ch + st]; r1s[ch] += r1s[ch + st]; }
        __syncthreads();
    }
    if (ch == 0) { g_fcB[0] = r0s[0] + fb[0]; g_fcB[1] = r1s[0] + fb[1]; }
}

// ---------------- final fc (folded BN): warp per row, fp16 y ----------------
__global__ void fc_k(const __half* __restrict__ y, float* __restrict__ out) {
    int gwarp = (blockIdx.x * blockDim.x + threadIdx.x) >> 5;
    int lane  = threadIdx.x & 31;
    if (gwarp >= BE) return;
    const __half2* row = (const __half2*)(y + (size_t)gwarp * Hh);
    float a0 = 0.f, a1 = 0.f;
    #pragma unroll
    for (int i = lane; i < 128; i += 32) {
        float2 v = __half22float2(row[i]);
        int ch = i * 2;
        a0 += v.x * g_fcW[ch*2 + 0] + v.y * g_fcW[ch*2 + 2];
        a1 += v.x * g_fcW[ch*2 + 1] + v.y * g_fcW[ch*2 + 3];
    }
    #pragma unroll
    for (int o = 16; o > 0; o >>= 1) {
        a0 += __shfl_down_sync(0xffffffffu, a0, o);
        a1 += __shfl_down_sync(0xffffffffu, a1, o);
    }
    if (lane == 0) {
        out[(size_t)gwarp * 2 + 0] = a0 + g_fcB[0];
        out[(size_t)gwarp * 2 + 1] = a1 + g_fcB[1];
    }
}

// ---------------------------------------------------------------------------
extern "C" void kernel_launch(void* const* d_in, const int* in_sizes, int n_in,
                              void* d_out, int out_size) {
    const float* inputs  = (const float*)d_in[0];
    const float* rel_rec = (const float*)d_in[1];
    const float* rel_snd = (const float*)d_in[2];
    const float* m1W1 = (const float*)d_in[3];  const float* m1b1 = (const float*)d_in[4];
    const float* m1W2 = (const float*)d_in[5];  const float* m1b2 = (const float*)d_in[6];
    const float* m2W1 = (const float*)d_in[7];  const float* m2b1 = (const float*)d_in[8];
    const float* m2W2 = (const float*)d_in[9];  const float* m2b2 = (const float*)d_in[10];
    const float* m3W1 = (const float*)d_in[11]; const float* m3b1 = (const float*)d_in[12];
    const float* m3W2 = (const float*)d_in[13]; const float* m3b2 = (const float*)d_in[14];
    const float* m4W1 = (const float*)d_in[15]; const float* m4b1 = (const float*)d_in[16];
    const float* m4W2 = (const float*)d_in[17]; const float* m4b2 = (const float*)d_in[18];
    const float* gmma = (const float*)d_in[19]; const float* beta = (const float*)d_in[20];
    const float* fcW  = (const float*)d_in[21]; const float* fcb  = (const float*)d_in[22];
    float* out = (float*)d_out;

    float *h1, *na, *nb, *as_, *ar_;
    __half *xskipH, *y4H, *wth, *wtl;
    cudaGetSymbolAddress((void**)&h1, g_h1);
    cudaGetSymbolAddress((void**)&na, g_na);
    cudaGetSymbolAddress((void**)&nb, g_nb);
    cudaGetSymbolAddress((void**)&as_, g_as);
    cudaGetSymbolAddress((void**)&ar_, g_ar);
    cudaGetSymbolAddress((void**)&xskipH, g_xskipH);
    cudaGetSymbolAddress((void**)&y4H, g_y4H);
    cudaGetSymbolAddress((void**)&wth, g_WtHi);
    cudaGetSymbolAddress((void**)&wtl, g_WtLo);

    cudaFuncSetAttribute(gemm_g1,  cudaFuncAttributeMaxDynamicSharedMemorySize, G1DS);
    cudaFuncSetAttribute(gemm_f23, cudaFuncAttributeMaxDynamicSharedMemorySize, F_DS);

    dim3 gN(BNr / 64, 4);
    dim3 gN2(BNr / 64, 8);
    dim3 tb(32, 32);
    dim3 tg(8, 8);

    // edge index tables + weight prep (transpose + fp16 split)
    build_idx_k<<<(Ee + 127) / 128, 128>>>(rel_rec, rel_snd);
    prep_wt_k<<<tg, tb>>>(m2W2,             wth + 0 * 65536, wtl + 0 * 65536);
    prep_wt_k<<<tg, tb>>>(m4W1 + 512 * 256, wth + 1 * 65536, wtl + 1 * 65536);
    prep_wt_k<<<tg, tb>>>(m4W2,             wth + 2 * 65536, wtl + 2 * 65536);

    // mlp1 (node level)
    gemm_node<<<gN, 256>>>(inputs, FIN, FIN, m1W1, m1b1, 1, na);
    gemm_node<<<gN, 256>>>(na, Hh, Hh, m1W2, m1b2, 1, h1);

    // node projections for mlp2 layer1 (send + recv halves, one launch)
    gemm_node2<<<gN2, 256>>>(h1, m2W1, m2W1 + 256*256, as_, ar_);

    // GEMM1 (1-term W): xskipH = fp16(ELU(ELU(as[s]+ar[r]+b1) @ W2 + b2))
    gemm_g1<<<NCTA, 512, G1DS>>>(wth + 0 * 65536, as_, ar_, m2b1, m2b2, xskipH);

    // edge2node + mlp3 (node level)
    edge2node_k<<<BNr, 256>>>(xskipH, na);
    gemm_node<<<gN, 256>>>(na, Hh, Hh, m3W1, m3b1, 1, nb);
    gemm_node<<<gN, 256>>>(nb, Hh, Hh, m3W2, m3b2, 1, h1);

    // node projections for mlp4 layer1
    gemm_node2<<<gN2, 256>>>(h1, m4W1, m4W1 + 256*256, as_, ar_);

    // fused GEMM2+GEMM3: y4H = fp16(ELU(ELU(xskipH@W4c + as[s]+ar[r]+b1) @ W4_2 + b2))
    //                     + fused per-CTA BN partial stats
    gemm_f23<<<NCTA, 512, F_DS>>>(xskipH,
                                  wth + 1 * 65536,
                                  wth + 2 * 65536, wtl + 2 * 65536,
                                  as_, ar_, m4b1, m4b2, y4H);

    // BN reduce (parallel deterministic), finalize, final fc
    bn_reduce_k<<<256, 256>>>();
    bn_fin3<<<1, 256>>>(gmma, beta, fcW, fcb);
    fc_k<<<(BE * 32 + 255) / 256, 256>>>(y4H, out);
}

// round 13
// speedup vs baseline: 2.7196x; 1.1302x over previous
#include <cuda_runtime.h>
#include <cuda_fp16.h>
#include <math.h>
#include <cstdint>

#define Bsz 32
#define Nn  100
#define Ee  9900
#define Hh  256
#define FIN 200
#define BE  (Bsz*Ee)    // 316800
#define BNr (Bsz*Nn)    // 3200
#define NCTA (BE/128)   // 2475

// ---------------- scratch (static device globals) ---------------------------
__device__ float g_h1[BNr*Hh];
__device__ float g_na[BNr*Hh];
__device__ float g_nb[BNr*Hh];
__device__ float g_as[BNr*Hh];
__device__ float g_ar[BNr*Hh];
__device__ __half g_xskipH[(size_t)BE*Hh];
__device__ __half g_y4H[(size_t)BE*Hh];
__device__ int   g_send[Ee];
__device__ int   g_recv[Ee];
__device__ float g_p3[(size_t)NCTA*256*2];   // per-CTA BN partials (sum, sumsq)
__device__ double g_chS[256], g_chQ[256];
__device__ float g_fcW[Hh*2];
__device__ float g_fcB[2];
// transposed fp16 weight images: [n][k] layout, 3 mats
__device__ __half g_WtHi[3][65536];
__device__ __half g_WtLo[3][65536];

__device__ __forceinline__ float elu_f(float x) { return x > 0.f ? x : expm1f(x); }
__device__ __forceinline__ float elu_fast(float x) {
    float e = __expf(fminf(x, 0.f)) - 1.f;
    return x > 0.f ? x : e;
}

__device__ __forceinline__ uint32_t smem_u32(const void* p) {
    uint32_t a;
    asm("{ .reg .u64 t; cvta.to.shared.u64 t, %1; cvt.u32.u64 %0, t; }" : "=r"(a) : "l"(p));
    return a;
}
__device__ __forceinline__ uint32_t pack_h2(__half a, __half b) {
    __half2 h2 = __halves2half2(a, b);
    return *reinterpret_cast<uint32_t*>(&h2);
}

#define LDSM4(r, addr) \
    asm volatile("ldmatrix.sync.aligned.m8n8.x4.shared.b16 {%0,%1,%2,%3}, [%4];" \
        : "=r"((r)[0]), "=r"((r)[1]), "=r"((r)[2]), "=r"((r)[3]) : "r"(addr))

#define MMA16816(d, a, b0, b1) \
    asm volatile("mma.sync.aligned.m16n8k16.row.col.f32.f16.f16.f32 " \
        "{%0,%1,%2,%3},{%4,%5,%6,%7},{%8,%9},{%0,%1,%2,%3};" \
        : "+f"((d)[0]), "+f"((d)[1]), "+f"((d)[2]), "+f"((d)[3]) \
        : "r"((a)[0]), "r"((a)[1]), "r"((a)[2]), "r"((a)[3]), "r"(b0), "r"(b1))

#define CP16(dst, src) \
    asm volatile("cp.async.ca.shared.global [%0], [%1], 16;" :: "r"(dst), "l"(src))
#define CP_COMMIT() asm volatile("cp.async.commit_group;" ::: "memory")
#define CP_WAIT0()  asm volatile("cp.async.wait_group 0;" ::: "memory")

// ---------------- edge index extraction -------------------------------------
__global__ void build_idx_k(const float* __restrict__ rr, const float* __restrict__ rs) {
    int e = blockIdx.x * blockDim.x + threadIdx.x;
    if (e >= Ee) return;
    int r = 0, s = 0;
    for (int n = 0; n < Nn; n++) {
        if (rr[e*Nn + n] > 0.5f) r = n;
        if (rs[e*Nn + n] > 0.5f) s = n;
    }
    g_recv[e] = r;
    g_send[e] = s;
}

// ---------------- weight prep: transpose [k][n]->[n][k] + fp16 split --------
__global__ void prep_wt_k(const float* __restrict__ W,
                          __half* __restrict__ Hi, __half* __restrict__ Lo) {
    __shared__ float t[32][33];
    int k0 = blockIdx.x * 32, n0 = blockIdx.y * 32;
    int tx = threadIdx.x, ty = threadIdx.y;
    t[ty][tx] = W[(k0 + ty) * 256 + n0 + tx];
    __syncthreads();
    float v = t[tx][ty];
    __half h = __float2half_rn(v);
    __half l = __float2half_rn(v - __half2float(h));
    Hi[(n0 + ty) * 256 + k0 + tx] = h;
    Lo[(n0 + ty) * 256 + k0 + tx] = l;
}

// ---------------- GEMM1: M128 x N256, 512 threads, 1-term W -----------------
#define ASTR  144
#define BHIOF  18432
#define G1BUF  55296
#define G1DS   (2*G1BUF)   // 110592

__global__ __launch_bounds__(512, 1)
void gemm_g1(const __half* __restrict__ WtHi,
             const float* __restrict__ As_, const float* __restrict__ Ar_,
             const float* __restrict__ b1,
             const float* __restrict__ bias,
             __half* __restrict__ Cout)
{
    extern __shared__ char sm[];
    __shared__ int sidx[128], ridx[128];

    const int tid  = threadIdx.x;
    const int lane = tid & 31, w = tid >> 5;
    const int row0 = blockIdx.x * 128;
    const uint32_t sbase = smem_u32(sm);

    const int rowA = tid >> 2;
    const int q0   = (tid & 3) * 16;

    #define CPB1(cc, bf) do { \
        _Pragma("unroll") \
        for (int i = 0; i < 4; ++i) { \
            int seg = tid + i * 512; \
            int rr = (seg >> 3) & 255; \
            int q  = seg & 7; \
            const __half* src = WtHi + (size_t)rr * 256 + (cc) * 64 + q * 8; \
            CP16(sbase + (bf) * G1BUF + BHIOF + rr * ASTR + q * 16, (const char*)src); \
        } \
    } while (0)

    #define STSA1(cc, bf) do { \
        char* adst = sm + (bf) * G1BUF + rowA * ASTR + q0 * 2; \
        _Pragma("unroll") \
        for (int it = 0; it < 2; ++it) { \
            int k0 = (cc) * 64 + q0 + it * 8; \
            float4 s0 = *(const float4*)(As_ + si + k0); \
            float4 s1 = *(const float4*)(As_ + si + k0 + 4); \
            float4 r0 = *(const float4*)(Ar_ + ri + k0); \
            float4 r1 = *(const float4*)(Ar_ + ri + k0 + 4); \
            float4 c0 = *(const float4*)(b1 + k0); \
            float4 c1 = *(const float4*)(b1 + k0 + 4); \
            float v0=elu_fast(s0.x+r0.x+c0.x), v1=elu_fast(s0.y+r0.y+c0.y); \
            float v2=elu_fast(s0.z+r0.z+c0.z), v3=elu_fast(s0.w+r0.w+c0.w); \
            float v4=elu_fast(s1.x+r1.x+c1.x), v5=elu_fast(s1.y+r1.y+c1.y); \
            float v6=elu_fast(s1.z+r1.z+c1.z), v7=elu_fast(s1.w+r1.w+c1.w); \
            uint4 o; \
            o.x = pack_h2(__float2half_rn(v0), __float2half_rn(v1)); \
            o.y = pack_h2(__float2half_rn(v2), __float2half_rn(v3)); \
            o.z = pack_h2(__float2half_rn(v4), __float2half_rn(v5)); \
            o.w = pack_h2(__float2half_rn(v6), __float2half_rn(v7)); \
            *(uint4*)(adst + it * 16) = o; \
        } \
    } while (0)

    CPB1(0, 0);
    CP_COMMIT();
    if (tid < 128) {
        int row = row0 + tid;
        int b = row / Ee, e = row - b * Ee;
        sidx[tid] = (b * Nn + g_send[e]) * Hh;
        ridx[tid] = (b * Nn + g_recv[e]) * Hh;
    }
    __syncthreads();
    const int si = sidx[rowA], ri = ridx[rowA];
    STSA1(0, 0);

    const int m0w = (w & 3) * 32;
    const int n0w = (w >> 2) * 64;
    const int laneA_row = (lane & 7) + ((lane >> 3) & 1) * 8;
    const int laneA_k   = ((lane >> 4) & 1) * 8;
    const int laneB_row = (lane & 7) + ((lane >> 4) & 1) * 8;
    const int laneB_k   = ((lane >> 3) & 1) * 8;

    uint32_t aOff[2], bOff[4];
    #pragma unroll
    for (int i = 0; i < 2; i++)
        aOff[i] = (uint32_t)((m0w + i*16 + laneA_row) * ASTR + laneA_k * 2);
    #pragma unroll
    for (int jp = 0; jp < 4; jp++)
        bOff[jp] = (uint32_t)(BHIOF + (n0w + jp*16 + laneB_row) * ASTR + laneB_k * 2);

    float acc[16][4];
    #pragma unroll
    for (int t = 0; t < 16; t++) { acc[t][0]=0.f; acc[t][1]=0.f; acc[t][2]=0.f; acc[t][3]=0.f; }

    #pragma unroll 1
    for (int c = 0; c < 4; ++c) {
        const int cur = c & 1, nxt = cur ^ 1;
        CP_WAIT0();
        __syncthreads();
        if (c < 3) {
            CPB1(c + 1, nxt);
            CP_COMMIT();
            STSA1(c + 1, nxt);
        }
        const uint32_t base = sbase + cur * G1BUF;
        #pragma unroll
        for (int ks = 0; ks < 4; ++ks) {
            uint32_t ah[2][4];
            #pragma unroll
            for (int i = 0; i < 2; i++)
                LDSM4(ah[i], base + aOff[i] + ks * 32);
            #pragma unroll
            for (int jp = 0; jp < 4; jp++) {
                uint32_t bh4[4];
                LDSM4(bh4, base + bOff[jp] + ks * 32);
                MMA16816(acc[0*8+2*jp],   ah[0], bh4[0], bh4[1]);
                MMA16816(acc[0*8+2*jp+1], ah[0], bh4[2], bh4[3]);
                MMA16816(acc[1*8+2*jp],   ah[1], bh4[0], bh4[1]);
                MMA16816(acc[1*8+2*jp+1], ah[1], bh4[2], bh4[3]);
            }
        }
    }

    const int g  = lane >> 2;
    const int tg = lane & 3;
    #pragma unroll
    for (int i = 0; i < 2; i++) {
        #pragma unroll
        for (int j = 0; j < 8; j++) {
            int colg = n0w + j*8 + tg*2;
            float b0v = __ldg(bias + colg), b1v = __ldg(bias + colg + 1);
            float* q = acc[i*8+j];
            int rlo = row0 + m0w + i*16 + g;
            int rhi = rlo + 8;
            float o0 = elu_fast(q[0] + b0v), o1 = elu_fast(q[1] + b1v);
            float o2 = elu_fast(q[2] + b0v), o3 = elu_fast(q[3] + b1v);
            *(uint32_t*)(Cout + (size_t)rlo * 256 + colg) = pack_h2(__float2half_rn(o0), __float2half_rn(o1));
            *(uint32_t*)(Cout + (size_t)rhi * 256 + colg) = pack_h2(__float2half_rn(o2), __float2half_rn(o3));
        }
    }
    #undef CPB1
    #undef STSA1
}

// ---------------- fused GEMM2+GEMM3 (both stages 1-term W) ------------------
// stage 1: pre = xskipH @ W1hi (fp32 acc)
// A2 = fp16(ELU(pre + As[s]+Ar[r]+b1)) resident in smem (stride 528)
// stage 2: y4 = fp16(ELU(A2 @ W2hi + b2)) + BN partials
#define F_STG   67584                 // staging region base (A2 = [0, 67584))
#define F_S1BUF 55296                 // stage-1: A1 18432 + B1hi 36864
#define F_S2BUF 36864                 // stage-2: Bhi only
#define F_DS    (F_STG + 2*F_S1BUF)   // 178176  (covers stage-1 peak; stage-2 needs only 67584+2*36864=141312)

__global__ __launch_bounds__(512, 1)
void gemm_f23(const __half* __restrict__ AmatH,
              const __half* __restrict__ W1Hi,
              const __half* __restrict__ W2Hi,
              const float* __restrict__ As_, const float* __restrict__ Ar_,
              const float* __restrict__ b1, const float* __restrict__ bias,
              __half* __restrict__ Cout)
{
    extern __shared__ char sm[];
    __shared__ int sidx[128], ridx[128];

    const int tid  = threadIdx.x;
    const int lane = tid & 31, w = tid >> 5;
    const int row0 = blockIdx.x * 128;
    const uint32_t sbase = smem_u32(sm);

    #define CPA1(cc, bf) do { \
        _Pragma("unroll") \
        for (int i = 0; i < 2; ++i) { \
            int seg = tid + i * 512; \
            int rr = seg >> 3, q = seg & 7; \
            const __half* src = AmatH + (size_t)(row0 + rr) * 256 + (cc) * 64 + q * 8; \
            CP16(sbase + F_STG + (bf) * F_S1BUF + rr * ASTR + q * 16, (const char*)src); \
        } \
    } while (0)
    #define CPB1f(cc, bf) do { \
        _Pragma("unroll") \
        for (int i = 0; i < 4; ++i) { \
            int seg = tid + i * 512; \
            int rr = (seg >> 3) & 255, q = seg & 7; \
            const __half* src = W1Hi + (size_t)rr * 256 + (cc) * 64 + q * 8; \
            CP16(sbase + F_STG + (bf) * F_S1BUF + 18432 + rr * ASTR + q * 16, (const char*)src); \
        } \
    } while (0)
    #define CPB2(cc, bf) do { \
        _Pragma("unroll") \
        for (int i = 0; i < 4; ++i) { \
            int seg = tid + i * 512; \
            int rr = (seg >> 3) & 255, q = seg & 7; \
            const __half* src = W2Hi + (size_t)rr * 256 + (cc) * 64 + q * 8; \
            CP16(sbase + F_STG + (bf) * F_S2BUF + rr * ASTR + q * 16, (const char*)src); \
        } \
    } while (0)

    // ---- prologue: stage-1 chunk 0
    CPA1(0, 0);
    CPB1f(0, 0);
    CP_COMMIT();
    if (tid < 128) {
        int row = row0 + tid;
        int b = row / Ee, e = row - b * Ee;
        sidx[tid] = (b * Nn + g_send[e]) * Hh;
        ridx[tid] = (b * Nn + g_recv[e]) * Hh;
    }

    const int m0w = (w & 3) * 32;
    const int n0w = (w >> 2) * 64;
    const int laneA_row = (lane & 7) + ((lane >> 3) & 1) * 8;
    const int laneA_k   = ((lane >> 4) & 1) * 8;
    const int laneB_row = (lane & 7) + ((lane >> 4) & 1) * 8;
    const int laneB_k   = ((lane >> 3) & 1) * 8;

    uint32_t aOff1[2], bOff1[4];
    #pragma unroll
    for (int i = 0; i < 2; i++)
        aOff1[i] = (uint32_t)((m0w + i*16 + laneA_row) * ASTR + laneA_k * 2);
    #pragma unroll
    for (int jp = 0; jp < 4; jp++)
        bOff1[jp] = (uint32_t)(18432 + (n0w + jp*16 + laneB_row) * ASTR + laneB_k * 2);

    float acc[16][4];
    #pragma unroll
    for (int t = 0; t < 16; t++) { acc[t][0]=0.f; acc[t][1]=0.f; acc[t][2]=0.f; acc[t][3]=0.f; }

    // ---- stage-1 mainloop (1-term)
    #pragma unroll 1
    for (int c = 0; c < 4; ++c) {
        const int cur = c & 1, nxt = cur ^ 1;
        CP_WAIT0();
        __syncthreads();
        if (c < 3) {
            CPA1(c + 1, nxt);
            CPB1f(c + 1, nxt);
            CP_COMMIT();
        }
        const uint32_t base = sbase + F_STG + cur * F_S1BUF;
        #pragma unroll
        for (int ks = 0; ks < 4; ++ks) {
            uint32_t ah[2][4];
            #pragma unroll
            for (int i = 0; i < 2; i++)
                LDSM4(ah[i], base + aOff1[i] + ks * 32);
            #pragma unroll
            for (int jp = 0; jp < 4; jp++) {
                uint32_t bh4[4];
                LDSM4(bh4, base + bOff1[jp] + ks * 32);
                MMA16816(acc[0*8+2*jp],   ah[0], bh4[0], bh4[1]);
                MMA16816(acc[0*8+2*jp+1], ah[0], bh4[2], bh4[3]);
                MMA16816(acc[1*8+2*jp],   ah[1], bh4[0], bh4[1]);
                MMA16816(acc[1*8+2*jp+1], ah[1], bh4[2], bh4[3]);
            }
        }
    }
    __syncthreads();   // all stage-1 LDSM/MMA done -> staging region reusable

    // ---- stage-2 B chunk 0 in flight while A2 is built
    CPB2(0, 0);
    CP_COMMIT();

    // ---- build A2 = fp16(ELU(pre + As[s]+Ar[r]+b1)) into [0, 67584)
    const int g  = lane >> 2;
    const int tg = lane & 3;
    #pragma unroll
    for (int i = 0; i < 2; ++i) {
        int lr0 = m0w + i*16 + g;
        int lr1 = lr0 + 8;
        int s0i = sidx[lr0], r0i = ridx[lr0];
        int s1i = sidx[lr1], r1i = ridx[lr1];
        #pragma unroll
        for (int j = 0; j < 8; ++j) {
            int colg = n0w + j*8 + tg*2;
            float2 sa0 = *(const float2*)(As_ + s0i + colg);
            float2 ra0 = *(const float2*)(Ar_ + r0i + colg);
            float2 sa1 = *(const float2*)(As_ + s1i + colg);
            float2 ra1 = *(const float2*)(Ar_ + r1i + colg);
            float2 bb  = *(const float2*)(b1 + colg);
            float* q4 = acc[i*8+j];
            float v0 = elu_fast(q4[0] + sa0.x + ra0.x + bb.x);
            float v1 = elu_fast(q4[1] + sa0.y + ra0.y + bb.y);
            float v2 = elu_fast(q4[2] + sa1.x + ra1.x + bb.x);
            float v3 = elu_fast(q4[3] + sa1.y + ra1.y + bb.y);
            *(uint32_t*)(sm + lr0 * 528 + colg * 2) = pack_h2(__float2half_rn(v0), __float2half_rn(v1));
            *(uint32_t*)(sm + lr1 * 528 + colg * 2) = pack_h2(__float2half_rn(v2), __float2half_rn(v3));
        }
    }
    #pragma unroll
    for (int t = 0; t < 16; t++) { acc[t][0]=0.f; acc[t][1]=0.f; acc[t][2]=0.f; acc[t][3]=0.f; }

    uint32_t aOff2[2], bOff2[4];
    #pragma unroll
    for (int i = 0; i < 2; i++)
        aOff2[i] = (uint32_t)((m0w + i*16 + laneA_row) * 528 + laneA_k * 2);
    #pragma unroll
    for (int jp = 0; jp < 4; jp++)
        bOff2[jp] = (uint32_t)(F_STG + (n0w + jp*16 + laneB_row) * ASTR + laneB_k * 2);

    // ---- stage-2 mainloop (1-term, A2 resident)
    #pragma unroll 1
    for (int c = 0; c < 4; ++c) {
        const int cur = c & 1, nxt = cur ^ 1;
        CP_WAIT0();
        __syncthreads();    // first pass also publishes A2 stores
        if (c < 3) {
            CPB2(c + 1, nxt);
            CP_COMMIT();
        }
        const uint32_t koA = (uint32_t)(c * 128);
        const uint32_t bbase = sbase + cur * F_S2BUF;
        #pragma unroll
        for (int ks = 0; ks < 4; ++ks) {
            uint32_t ah[2][4];
            #pragma unroll
            for (int i = 0; i < 2; i++)
                LDSM4(ah[i], sbase + aOff2[i] + koA + ks * 32);
            #pragma unroll
            for (int jp = 0; jp < 4; jp++) {
                uint32_t bh4[4];
                LDSM4(bh4, bbase + bOff2[jp] + ks * 32);
                MMA16816(acc[0*8+2*jp],   ah[0], bh4[0], bh4[1]);
                MMA16816(acc[0*8+2*jp+1], ah[0], bh4[2], bh4[3]);
                MMA16816(acc[1*8+2*jp],   ah[1], bh4[0], bh4[1]);
                MMA16816(acc[1*8+2*jp+1], ah[1], bh4[2], bh4[3]);
            }
        }
    }

    // ---- epilogue: bias + ELU + fp16 stores + BN partials
    float cs[16], cq[16];
    #pragma unroll
    for (int t = 0; t < 16; ++t) { cs[t] = 0.f; cq[t] = 0.f; }
    #pragma unroll
    for (int i = 0; i < 2; i++) {
        #pragma unroll
        for (int j = 0; j < 8; j++) {
            int colg = n0w + j*8 + tg*2;
            float b0v = __ldg(bias + colg), b1v = __ldg(bias + colg + 1);
            float* q = acc[i*8+j];
            int rlo = row0 + m0w + i*16 + g;
            int rhi = rlo + 8;
            float o0 = elu_fast(q[0] + b0v), o1 = elu_fast(q[1] + b1v);
            float o2 = elu_fast(q[2] + b0v), o3 = elu_fast(q[3] + b1v);
            cs[j*2+0] += o0 + o2;
            cs[j*2+1] += o1 + o3;
            cq[j*2+0] += o0*o0 + o2*o2;
            cq[j*2+1] += o1*o1 + o3*o3;
            *(uint32_t*)(Cout + (size_t)rlo * 256 + colg) = pack_h2(__float2half_rn(o0), __float2half_rn(o1));
            *(uint32_t*)(Cout + (size_t)rhi * 256 + colg) = pack_h2(__float2half_rn(o2), __float2half_rn(o3));
        }
    }

    #pragma unroll
    for (int t = 0; t < 16; ++t) {
        #pragma unroll
        for (int o = 4; o <= 16; o <<= 1) {
            cs[t] += __shfl_xor_sync(0xffffffffu, cs[t], o);
            cq[t] += __shfl_xor_sync(0xffffffffu, cq[t], o);
        }
    }
    __syncthreads();
    float* sps = (float*)sm;          // [16 warps][64 local cols][2]
    if (lane < 4) {
        #pragma unroll
        for (int j = 0; j < 8; ++j) {
            #pragma unroll
            for (int par = 0; par < 2; ++par) {
                int coll = j*8 + lane*2 + par;
                sps[w*128 + coll*2 + 0] = cs[j*2+par];
                sps[w*128 + coll*2 + 1] = cq[j*2+par];
            }
        }
    }
    __syncthreads();
    int col = tid >> 1, stat = tid & 1;
    int nw4 = (col >> 6) * 4;
    float a2 = 0.f;
    #pragma unroll
    for (int mw = 0; mw < 4; ++mw)
        a2 += sps[(nw4 + mw)*128 + (col & 63)*2 + stat];
    g_p3[((size_t)blockIdx.x * 256 + col)*2 + stat] = a2;
    #undef CPA1
    #undef CPB1f
    #undef CPB2
}

// ---------------- small node-level SIMT GEMM (M=3200) -----------------------
__global__ __launch_bounds__(256)
void gemm_node(const float* __restrict__ A, int lda, int K,
               const float* __restrict__ W, const float* __restrict__ bias,
               int do_elu, float* __restrict__ C)
{
    __shared__ float sA[16][65];
    __shared__ float sB[16][64];
    const int row0 = blockIdx.x * 64;
    const int col0 = blockIdx.y * 64;
    const int tid  = threadIdx.x;
    const int ty   = tid >> 4, tx = tid & 15;
    float acc[4][4] = {};
    for (int kt = 0; kt < K; kt += 16) {
        #pragma unroll
        for (int i = 0; i < 4; i++) {
            int idx = tid + i * 256;
            int m = idx >> 4, k = idx & 15;
            int kk = kt + k;
            sA[k][m] = (kk < K) ? A[(size_t)(row0 + m) * lda + kk] : 0.f;
        }
        #pragma unroll
        for (int i = 0; i < 4; i++) {
            int idx = tid + i * 256;
            int k = idx >> 6, n = idx & 63;
            int kk = kt + k;
            sB[k][n] = (kk < K) ? W[(size_t)kk * 256 + col0 + n] : 0.f;
        }
        __syncthreads();
        #pragma unroll
        for (int k = 0; k < 16; k++) {
            float a[4], b[4];
            #pragma unroll
            for (int i = 0; i < 4; i++) a[i] = sA[k][ty*4 + i];
            #pragma unroll
            for (int j = 0; j < 4; j++) b[j] = sB[k][tx*4 + j];
            #pragma unroll
            for (int i = 0; i < 4; i++)
                #pragma unroll
                for (int j = 0; j < 4; j++)
                    acc[i][j] += a[i] * b[j];
        }
        __syncthreads();
    }
    #pragma unroll
    for (int i = 0; i < 4; i++) {
        int m = row0 + ty*4 + i;
        #pragma unroll
        for (int j = 0; j < 4; j++) {
            int n = col0 + tx*4 + j;
            float v = acc[i][j];
            if (bias) v += bias[n];
            if (do_elu) v = elu_f(v);
            C[(size_t)m * 256 + n] = v;
        }
    }
}

// ---------------- merged dual node GEMM: same A, two weight mats ------------
__global__ __launch_bounds__(256)
void gemm_node2(const float* __restrict__ A,
                const float* __restrict__ Wa, const float* __restrict__ Wb,
                float* __restrict__ Ca, float* __restrict__ Cb)
{
    const float* W = (blockIdx.y < 4) ? Wa : Wb;
    float* C       = (blockIdx.y < 4) ? Ca : Cb;
    const int col0 = (blockIdx.y & 3) * 64;
    __shared__ float sA[16][65];
    __shared__ float sB[16][64];
    const int row0 = blockIdx.x * 64;
    const int tid  = threadIdx.x;
    const int ty   = tid >> 4, tx = tid & 15;
    float acc[4][4] = {};
    for (int kt = 0; kt < 256; kt += 16) {
        #pragma unroll
        for (int i = 0; i < 4; i++) {
            int idx = tid + i * 256;
            int m = idx >> 4, k = idx & 15;
            sA[k][m] = A[(size_t)(row0 + m) * 256 + kt + k];
        }
        #pragma unroll
        for (int i = 0; i < 4; i++) {
            int idx = tid + i * 256;
            int k = idx >> 6, n = idx & 63;
            sB[k][n] = W[(size_t)(kt + k) * 256 + col0 + n];
        }
        __syncthreads();
        #pragma unroll
        for (int k = 0; k < 16; k++) {
            float a[4], b[4];
            #pragma unroll
            for (int i = 0; i < 4; i++) a[i] = sA[k][ty*4 + i];
            #pragma unroll
            for (int j = 0; j < 4; j++) b[j] = sB[k][tx*4 + j];
            #pragma unroll
            for (int i = 0; i < 4; i++)
                #pragma unroll
                for (int j = 0; j < 4; j++)
                    acc[i][j] += a[i] * b[j];
        }
        __syncthreads();
    }
    #pragma unroll
    for (int i = 0; i < 4; i++) {
        int m = row0 + ty*4 + i;
        #pragma unroll
        for (int j = 0; j < 4; j++)
            C[(size_t)m * 256 + col0 + tx*4 + j] = acc[i][j];
    }
}

// ---------------- edge2node: contiguous 99-edge segment mean (fp16 in) ------
__global__ void edge2node_k(const __half* __restrict__ x, float* __restrict__ out) {
    int nodeRow = blockIdx.x;
    int h = threadIdx.x;
    int b = nodeRow / Nn, n = nodeRow - b * Nn;
    const __half* base = x + (size_t)(b * Ee + n * 99) * Hh + h;
    float s = 0.f;
    #pragma unroll 3
    for (int r = 0; r < 99; r++) s += __half2float(base[(size_t)r * Hh]);
    out[(size_t)nodeRow * Hh + h] = s * (1.0f / 9900.0f);
}

// ---------------- BN partial reduce: parallel deterministic tree ------------
__global__ void bn_reduce_k() {
    int ch = blockIdx.x, t = threadIdx.x;
    double s = 0.0, q = 0.0;
    for (int bx = t; bx < NCTA; bx += 256) {
        s += (double)g_p3[((size_t)bx * 256 + ch) * 2 + 0];
        q += (double)g_p3[((size_t)bx * 256 + ch) * 2 + 1];
    }
    __shared__ double ss[256], sq[256];
    ss[t] = s; sq[t] = q;
    __syncthreads();
    for (int st = 128; st > 0; st >>= 1) {
        if (t < st) { ss[t] += ss[t + st]; sq[t] += sq[t + st]; }
        __syncthreads();
    }
    if (t == 0) { g_chS[ch] = ss[0]; g_chQ[ch] = sq[0]; }
}

// ---------------- BN finalize + fold into fc --------------------------------
__global__ void bn_fin3(const float* __restrict__ gamma, const float* __restrict__ beta,
                        const float* __restrict__ W, const float* __restrict__ fb) {
    int ch = threadIdx.x;
    double s = g_chS[ch], q = g_chQ[ch];
    double m = s / (double)BE;
    double v = q / (double)BE - m * m;
    float sc = (float)(rsqrt(v + 1e-5) * (double)gamma[ch]);
    float sh = beta[ch] - (float)m * sc;
    float w0 = W[ch*2 + 0], w1 = W[ch*2 + 1];
    g_fcW[ch*2 + 0] = sc * w0;
    g_fcW[ch*2 + 1] = sc * w1;
    __shared__ float r0s[256], r1s[256];
    r0s[ch] = sh * w0;
    r1s[ch] = sh * w1;
    __syncthreads();
    for (int st = 128; st > 0; st >>= 1) {
        if (ch < st) { r0s[ch] += r0s[ch + st]; r1s[ch] += r1s[ch + st]; }
        __syncthreads();
    }
    if (ch == 0) { g_fcB[0] = r0s[0] + fb[0]; g_fcB[1] = r1s[0] + fb[1]; }
}

// ---------------- final fc (folded BN): warp per row, fp16 y ----------------
__global__ void fc_k(const __half* __restrict__ y, float* __restrict__ out) {
    int gwarp = (blockIdx.x * blockDim.x + threadIdx.x) >> 5;
    int lane  = threadIdx.x & 31;
    if (gwarp >= BE) return;
    const __half2* row = (const __half2*)(y + (size_t)gwarp * Hh);
    float a0 = 0.f, a1 = 0.f;
    #pragma unroll
    for (int i = lane; i < 128; i += 32) {
        float2 v = __half22float2(row[i]);
        int ch = i * 2;
        a0 += v.x * g_fcW[ch*2 + 0] + v.y * g_fcW[ch*2 + 2];
        a1 += v.x * g_fcW[ch*2 + 1] + v.y * g_fcW[ch*2 + 3];
    }
    #pragma unroll
    for (int o = 16; o > 0; o >>= 1) {
        a0 += __shfl_down_sync(0xffffffffu, a0, o);
        a1 += __shfl_down_sync(0xffffffffu, a1, o);
    }
    if (lane == 0) {
        out[(size_t)gwarp * 2 + 0] = a0 + g_fcB[0];
        out[(size_t)gwarp * 2 + 1] = a1 + g_fcB[1];
    }
}

// ---------------------------------------------------------------------------
extern "C" void kernel_launch(void* const* d_in, const int* in_sizes, int n_in,
                              void* d_out, int out_size) {
    const float* inputs  = (const float*)d_in[0];
    const float* rel_rec = (const float*)d_in[1];
    const float* rel_snd = (const float*)d_in[2];
    const float* m1W1 = (const float*)d_in[3];  const float* m1b1 = (const float*)d_in[4];
    const float* m1W2 = (const float*)d_in[5];  const float* m1b2 = (const float*)d_in[6];
    const float* m2W1 = (const float*)d_in[7];  const float* m2b1 = (const float*)d_in[8];
    const float* m2W2 = (const float*)d_in[9];  const float* m2b2 = (const float*)d_in[10];
    const float* m3W1 = (const float*)d_in[11]; const float* m3b1 = (const float*)d_in[12];
    const float* m3W2 = (const float*)d_in[13]; const float* m3b2 = (const float*)d_in[14];
    const float* m4W1 = (const float*)d_in[15]; const float* m4b1 = (const float*)d_in[16];
    const float* m4W2 = (const float*)d_in[17]; const float* m4b2 = (const float*)d_in[18];
    const float* gmma = (const float*)d_in[19]; const float* beta = (const float*)d_in[20];
    const float* fcW  = (const float*)d_in[21]; const float* fcb  = (const float*)d_in[22];
    float* out = (float*)d_out;

    float *h1, *na, *nb, *as_, *ar_;
    __half *xskipH, *y4H, *wth, *wtl;
    cudaGetSymbolAddress((void**)&h1, g_h1);
    cudaGetSymbolAddress((void**)&na, g_na);
    cudaGetSymbolAddress((void**)&nb, g_nb);
    cudaGetSymbolAddress((void**)&as_, g_as);
    cudaGetSymbolAddress((void**)&ar_, g_ar);
    cudaGetSymbolAddress((void**)&xskipH, g_xskipH);
    cudaGetSymbolAddress((void**)&y4H, g_y4H);
    cudaGetSymbolAddress((void**)&wth, g_WtHi);
    cudaGetSymbolAddress((void**)&wtl, g_WtLo);

    cudaFuncSetAttribute(gemm_g1,  cudaFuncAttributeMaxDynamicSharedMemorySize, G1DS);
    cudaFuncSetAttribute(gemm_f23, cudaFuncAttributeMaxDynamicSharedMemorySize, F_DS);

    dim3 gN(BNr / 64, 4);
    dim3 gN2(BNr / 64, 8);
    dim3 tb(32, 32);
    dim3 tg(8, 8);

    // edge index tables + weight prep (transpose + fp16)
    build_idx_k<<<(Ee + 127) / 128, 128>>>(rel_rec, rel_snd);
    prep_wt_k<<<tg, tb>>>(m2W2,             wth + 0 * 65536, wtl + 0 * 65536);
    prep_wt_k<<<tg, tb>>>(m4W1 + 512 * 256, wth + 1 * 65536, wtl + 1 * 65536);
    prep_wt_k<<<tg, tb>>>(m4W2,             wth + 2 * 65536, wtl + 2 * 65536);

    // mlp1 (node level)
    gemm_node<<<gN, 256>>>(inputs, FIN, FIN, m1W1, m1b1, 1, na);
    gemm_node<<<gN, 256>>>(na, Hh, Hh, m1W2, m1b2, 1, h1);

    // node projections for mlp2 layer1 (send + recv halves, one launch)
    gemm_node2<<<gN2, 256>>>(h1, m2W1, m2W1 + 256*256, as_, ar_);

    // GEMM1 (1-term W): xskipH = fp16(ELU(ELU(as[s]+ar[r]+b1) @ W2 + b2))
    gemm_g1<<<NCTA, 512, G1DS>>>(wth + 0 * 65536, as_, ar_, m2b1, m2b2, xskipH);

    // edge2node + mlp3 (node level)
    edge2node_k<<<BNr, 256>>>(xskipH, na);
    gemm_node<<<gN, 256>>>(na, Hh, Hh, m3W1, m3b1, 1, nb);
    gemm_node<<<gN, 256>>>(nb, Hh, Hh, m3W2, m3b2, 1, h1);

    // node projections for mlp4 layer1
    gemm_node2<<<gN2, 256>>>(h1, m4W1, m4W1 + 256*256, as_, ar_);

    // fused GEMM2+GEMM3 (both 1-term): y4H = fp16(ELU(ELU(xskipH@W4c + as[s]+ar[r]+b1) @ W4_2 + b2))
    //                                   + fused per-CTA BN partial stats
    gemm_f23<<<NCTA, 512, F_DS>>>(xskipH,
                                  wth + 1 * 65536,
                                  wth + 2 * 65536,
                                  as_, ar_, m4b1, m4b2, y4H);

    // BN reduce (parallel deterministic), finalize, final fc
    bn_reduce_k<<<256, 256>>>();
    bn_fin3<<<1, 256>>>(gmma, beta, fcW, fcb);
    fc_k<<<(BE * 32 + 255) / 256, 256>>>(y4H, out);
}